// round 13
// baseline (speedup 1.0000x reference)
#include <cuda_runtime.h>
#include <cuda.h>
#include <cuda_bf16.h>
#include <cstdint>

#define SEQ 8192
#define DIM 1024

// tcgen05 is only legal when compiling the arch-specific (sm_103a) device pass.
#if (defined(__CUDA_ARCH_FEAT_SM103_ALL) || (defined(__CUDA_ARCH_SPECIFIC__) && (__CUDA_ARCH_SPECIFIC__ == 1030)))
#define TC_PATH 1
#else
#define TC_PATH 0
#endif

// ---- device scratch (no allocations allowed) ----
__device__ float g_xh[SEQ * DIM], g_xl[SEQ * DIM];          // x hi/lo fp32 (k-major)
__device__ float g_wqth[DIM * DIM], g_wqtl[DIM * DIM];      // Wq^T hi/lo
__device__ float g_wkth[DIM * DIM], g_wktl[DIM * DIM];      // Wk^T hi/lo
__device__ float g_wvt[DIM * DIM];                          // Wv^T (tf32)
__device__ float g_qh[SEQ * DIM], g_ql[SEQ * DIM];          // Q hi/lo fp32 (fallback)
__device__ __nv_bfloat16 g_qb[SEQ * 2 * DIM];               // Q bf16 interleaved [hi16|lo16]
__device__ float g_kh[SEQ * DIM], g_kl[SEQ * DIM];          // K hi/lo fp32 (fallback)
__device__ __nv_bfloat16 g_kb[SEQ * 2 * DIM];               // K bf16 interleaved
__device__ float g_vt[(size_t)DIM * SEQ];                   // V^T (tf32) [DIM, SEQ]
__device__ float g_s[(size_t)SEQ * SEQ];                    // scores / weights

// ---------------------------------------------------------------------------
// Common helpers
// ---------------------------------------------------------------------------
__device__ __forceinline__ float f2tf32(float f) {
    uint32_t r;
    asm("cvt.rna.tf32.f32 %0, %1;" : "=r"(r) : "f"(f));
    return __uint_as_float(r);
}
__device__ __forceinline__ uint32_t smem_u32(const void* p) {
    uint32_t a;
    asm("{ .reg .u64 t; cvta.to.shared.u64 t, %1; cvt.u32.u64 %0, t; }" : "=r"(a) : "l"(p));
    return a;
}
__device__ __forceinline__ void cp_async16(float* smem_dst, const float* gmem_src) {
    uint32_t s = (uint32_t)__cvta_generic_to_shared(smem_dst);
    asm volatile("cp.async.cg.shared.global [%0], [%1], 16;\n" :: "r"(s), "l"(gmem_src));
}
__device__ __forceinline__ void cp_commit() { asm volatile("cp.async.commit_group;\n"); }
template <int N>
__device__ __forceinline__ void cp_wait() { asm volatile("cp.async.wait_group %0;\n" :: "n"(N)); }

__device__ __forceinline__ void mma_sync_tf32(float* d, const uint32_t* a, const uint32_t* b) {
    asm volatile(
        "mma.sync.aligned.m16n8k8.row.col.f32.tf32.tf32.f32 "
        "{%0,%1,%2,%3}, {%4,%5,%6,%7}, {%8,%9}, {%0,%1,%2,%3};\n"
        : "+f"(d[0]), "+f"(d[1]), "+f"(d[2]), "+f"(d[3])
        : "r"(a[0]), "r"(a[1]), "r"(a[2]), "r"(a[3]), "r"(b[0]), "r"(b[1]));
}

// ---------------------------------------------------------------------------
// mbarrier / TMA helpers
// ---------------------------------------------------------------------------
__device__ __forceinline__ void mbar_init(uint32_t a, uint32_t cnt) {
    asm volatile("mbarrier.init.shared.b64 [%0], %1;" :: "r"(a), "r"(cnt) : "memory");
}
__device__ __forceinline__ void mbar_expect(uint32_t a, uint32_t bytes) {
    asm volatile("mbarrier.arrive.expect_tx.shared.b64 _, [%0], %1;" :: "r"(a), "r"(bytes) : "memory");
}
__device__ __forceinline__ void mbar_wait(uint32_t a, uint32_t parity) {
    asm volatile(
        "{\n\t"
        ".reg .pred P1;\n\t"
        "LAB_WAIT%=:\n\t"
        "mbarrier.try_wait.parity.acquire.cta.shared::cta.b64 P1, [%0], %1, 0x989680;\n\t"
        "@P1 bra LAB_DONE%=;\n\t"
        "bra LAB_WAIT%=;\n\t"
        "LAB_DONE%=:\n\t"
        "}"
        :: "r"(a), "r"(parity) : "memory");
}
__device__ __forceinline__ void tma3d(uint32_t dst, const CUtensorMap* m, int x, int y, uint32_t mbar) {
    asm volatile(
        "cp.async.bulk.tensor.3d.shared::cta.global.tile.mbarrier::complete_tx::bytes "
        "[%0], [%1, {%2, %3, %4}], [%5];"
        :: "r"(dst), "l"(m), "r"(x), "r"(y), "r"(0), "r"(mbar) : "memory");
}
#if TC_PATH
__device__ __forceinline__ void tc_alloc(uint32_t smem_result, uint32_t ncols) {
    asm volatile("tcgen05.alloc.cta_group::1.sync.aligned.shared::cta.b32 [%0], %1;"
                 :: "r"(smem_result), "r"(ncols) : "memory");
}
__device__ __forceinline__ void tc_dealloc(uint32_t tmem, uint32_t ncols) {
    asm volatile("tcgen05.dealloc.cta_group::1.sync.aligned.b32 %0, %1;" :: "r"(tmem), "r"(ncols));
}
__device__ __forceinline__ void tc_commit(uint32_t mbar) {
    asm volatile("tcgen05.commit.cta_group::1.mbarrier::arrive::one.shared::cluster.b64 [%0];"
                 :: "r"(mbar) : "memory");
}
__device__ __forceinline__ void tc_fence_after() {
    asm volatile("tcgen05.fence::after_thread_sync;" ::: "memory");
}
__device__ __forceinline__ void tc_wait_ld() {
    asm volatile("tcgen05.wait::ld.sync.aligned;" ::: "memory");
}
__device__ __forceinline__ void tc_ld_x32(uint32_t* r, uint32_t tmem) {
    asm volatile(
        "tcgen05.ld.sync.aligned.32x32b.x32.b32 "
        "{%0, %1, %2, %3, %4, %5, %6, %7, %8, %9, %10, %11, %12, %13, %14, %15, "
        " %16, %17, %18, %19, %20, %21, %22, %23, %24, %25, %26, %27, %28, %29, %30, %31}, [%32];"
        : "=r"(r[0]), "=r"(r[1]), "=r"(r[2]), "=r"(r[3]), "=r"(r[4]), "=r"(r[5]), "=r"(r[6]), "=r"(r[7]),
          "=r"(r[8]), "=r"(r[9]), "=r"(r[10]), "=r"(r[11]), "=r"(r[12]), "=r"(r[13]), "=r"(r[14]), "=r"(r[15]),
          "=r"(r[16]), "=r"(r[17]), "=r"(r[18]), "=r"(r[19]), "=r"(r[20]), "=r"(r[21]), "=r"(r[22]), "=r"(r[23]),
          "=r"(r[24]), "=r"(r[25]), "=r"(r[26]), "=r"(r[27]), "=r"(r[28]), "=r"(r[29]), "=r"(r[30]), "=r"(r[31])
        : "r"(tmem));
}
__device__ __forceinline__ void mma_ss_tf32(uint32_t d, uint64_t a, uint64_t b, uint32_t idesc, uint32_t en) {
    asm volatile(
        "{\n\t"
        ".reg .pred p;\n\t"
        "setp.ne.u32 p, %4, 0;\n\t"
        "tcgen05.mma.cta_group::1.kind::tf32 [%0], %1, %2, %3, {%5, %5, %5, %5}, p;\n\t"
        "}"
        :: "r"(d), "l"(a), "l"(b), "r"(idesc), "r"(en), "r"(0u) : "memory");
}
__device__ __forceinline__ void mma_ss_bf16(uint32_t d, uint64_t a, uint64_t b, uint32_t idesc, uint32_t en) {
    asm volatile(
        "{\n\t"
        ".reg .pred p;\n\t"
        "setp.ne.u32 p, %4, 0;\n\t"
        "tcgen05.mma.cta_group::1.kind::f16 [%0], %1, %2, %3, {%5, %5, %5, %5}, p;\n\t"
        "}"
        :: "r"(d), "l"(a), "l"(b), "r"(idesc), "r"(en), "r"(0u) : "memory");
}
#endif

// SW64 smem descriptor (K-major, 64B rows): layout=SW64(4), version=1, SBO=32, LBO=1
static constexpr uint64_t DESC_BASE_SW64 =
    (4ull << 61) | (1ull << 46) | (32ull << 32) | (1ull << 16);
__device__ __forceinline__ uint64_t make_desc64(uint32_t addr) {
    return DESC_BASE_SW64 | ((uint64_t)(addr >> 4) & 0x3FFF);
}

// ---------------------------------------------------------------------------
// Unified GEMM: C[M, Ntot] = A[M, K] * B[Ntot, K]^T.
// NMMA==1: tf32 1x (fp32 operands holding exact tf32 values).
// NMMA==3: tf32 3-term hi/lo compensation (fp32 hi + fp32 lo tiles).
// NMMA==2: PURE bf16 3-term: operands are bf16 interleaved [hi16|lo16] per
//          16-K group; hi*hi + hi*lo + lo*hi at kind::f16 K=16. Traffic AND
//          MMA cycles both halved vs NMMA==3 (the R8-R12 co-saturation fix).
// CTA tile 256x256 (two M=128 halves -> TMEM 512 cols), BK=16, 64-byte rows,
// SW64, 3-stage TMA pipeline with DEFERRED done-waits (R12), 256 threads.
// EPI: 0=raw, 1=tf32-rounded, 2=fp32 hi/lo split, 3=split + bf16 interleaved.
// ---------------------------------------------------------------------------
constexpr int BM = 256, BN = 256, BK = 16;
constexpr int MH = 128;
constexpr uint32_t IDESC_TF32 =
    (1u << 4) | (2u << 7) | (2u << 10) | ((BN / 8) << 17) | ((MH / 16) << 24);
constexpr uint32_t IDESC_BF16 =
    (1u << 4) | (1u << 7) | (1u << 10) | ((BN / 8) << 17) | ((MH / 16) << 24);

template <int NMMA, int EPI>
__global__ __launch_bounds__(256, 1)
void tc_gemm(const __grid_constant__ CUtensorMap tmA0,
             const __grid_constant__ CUtensorMap tmA1,
             const __grid_constant__ CUtensorMap tmB0,
             const __grid_constant__ CUtensorMap tmB1,
             const float* __restrict__ Ah, const float* __restrict__ Al,
             const float* __restrict__ Bh, const float* __restrict__ Bl,
             float* __restrict__ C0, float* __restrict__ C1,
             __nv_bfloat16* __restrict__ Cb,
             int Ntot, int Ktot)
{
    extern __shared__ __align__(16) float smem[];
    const int tid = threadIdx.x;
    const int bn = blockIdx.x * BN;
    const int bm = blockIdx.y * BM;
    const int NT = Ktot / BK;

#if TC_PATH
    // ======================= tcgen05 + TMA path (SW64) =======================
    constexpr int T_BYTES = 16384;           // each tile: 256 rows x 64 B
    constexpr int NTILE = (NMMA == 3) ? 4 : 2;   // NMMA 1/2 -> A + B only
    constexpr int STAGE = NTILE * T_BYTES;
    constexpr int NS = 3;
    constexpr uint32_t AH1 = 512;            // M half-1 desc offset: 8 KB / 16

    __shared__ __align__(8) uint64_t mbar_store[2 * NS];
    __shared__ uint32_t tmem_ptr;

    const int wid = tid >> 5;
    const int lid = tid & 31;
    const uint32_t sbase = (smem_u32(smem) + 1023) & ~1023u;
    uint32_t mb_full[NS], mb_done[NS];
    #pragma unroll
    for (int s = 0; s < NS; s++) {
        mb_full[s] = smem_u32(&mbar_store[s]);
        mb_done[s] = smem_u32(&mbar_store[NS + s]);
    }

    if (wid == 0) tc_alloc(smem_u32(&tmem_ptr), 512);
    if (tid == 0) {
        #pragma unroll
        for (int s = 0; s < NS; s++) { mbar_init(mb_full[s], 1); mbar_init(mb_done[s], 1); }
    }
    __syncthreads();
    const uint32_t tmem = tmem_ptr;      // D0 = cols 0-255, D1 = cols 256-511

    if (tid == 0) {
        uint32_t pf[NS] = {};
        const uint32_t boff = (NMMA == 3) ? 2 * T_BYTES : T_BYTES;

        auto issue = [&](int it, int s) {
            const uint32_t st = sbase + (uint32_t)s * STAGE;
            const int k0 = it * BK;
            mbar_expect(mb_full[s], (uint32_t)STAGE);
            if (NMMA == 2) {
                // bf16 maps: x-coord in bf16 elements = 2 * logical k
                tma3d(st,          &tmA0, 2 * k0, bm, mb_full[s]);
                tma3d(st + boff,   &tmB0, 2 * k0, bn, mb_full[s]);
            } else {
                tma3d(st, &tmA0, k0, bm, mb_full[s]);
                if (NMMA == 3) tma3d(st + T_BYTES, &tmA1, k0, bm, mb_full[s]);
                tma3d(st + boff, &tmB0, k0, bn, mb_full[s]);
                if (NMMA == 3) tma3d(st + boff + T_BYTES, &tmB1, k0, bn, mb_full[s]);
            }
        };

        #pragma unroll
        for (int s = 0; s < NS; s++)
            if (s < NT) issue(s, s);

        for (int it = 0; it < NT; it++) {
            const int s = it % NS;
            mbar_wait(mb_full[s], pf[s]); pf[s] ^= 1;

            const uint32_t st = sbase + (uint32_t)s * STAGE;
            const uint64_t da0 = make_desc64(st);
            const uint64_t db0 = make_desc64(st + boff);
            const uint64_t da1 = make_desc64(st + T_BYTES);          // tf32 lo (NMMA3)
            const uint64_t db1 = make_desc64(st + boff + T_BYTES);

            if (NMMA == 2) {
                // one K=16 sub-chunk per BK=16: hi at +0, lo at +2 (32 B)
                const uint32_t en0 = (it > 0) ? 1u : 0u;
                #pragma unroll
                for (int h = 0; h < 2; h++) {
                    const uint32_t d = tmem + h * 256;
                    const uint64_t ha = h * (uint64_t)AH1;
                    mma_ss_bf16(d, da0 + ha,     db0,     IDESC_BF16, en0); // hi*hi
                    mma_ss_bf16(d, da0 + ha,     db0 + 2, IDESC_BF16, 1u);  // hi*lo
                    mma_ss_bf16(d, da0 + ha + 2, db0,     IDESC_BF16, 1u);  // lo*hi
                }
            } else {
                #pragma unroll
                for (int ks = 0; ks < 2; ks++) {            // two K=8 steps
                    const uint64_t o = 2 * ks;
                    const uint32_t en0 = (it > 0 || ks > 0) ? 1u : 0u;
                    #pragma unroll
                    for (int h = 0; h < 2; h++) {
                        const uint32_t d = tmem + h * 256;
                        const uint64_t ha = h * (uint64_t)AH1;
                        if (NMMA == 3) {
                            mma_ss_tf32(d, da0 + ha + o, db1 + o, IDESC_TF32, en0);
                            mma_ss_tf32(d, da1 + ha + o, db0 + o, IDESC_TF32, 1u);
                            mma_ss_tf32(d, da0 + ha + o, db0 + o, IDESC_TF32, 1u);
                        } else {
                            mma_ss_tf32(d, da0 + ha + o, db0 + o, IDESC_TF32, en0);
                        }
                    }
                }
            }
            tc_commit(mb_done[s]);

            // Deferred refill (R12): current chunk's MMAs already queued keep
            // the tensor pipe busy while we wait on the PREVIOUS chunk.
            const int prev = it - 1;
            if (prev >= 0 && prev + NS < NT) {
                const int sp = prev % NS;
                mbar_wait(mb_done[sp], (uint32_t)((prev / NS) & 1));
                issue(prev + NS, sp);
            }
        }
        mbar_wait(mb_done[(NT - 1) % NS], (uint32_t)(((NT - 1) / NS) & 1));
    }
    __syncthreads();
    tc_fence_after();

    // epilogue: warps 0-3; each D half is 128 rows x 256 cols fp32
    if (wid < 4) {
        #pragma unroll
        for (int h = 0; h < 2; h++) {
            const size_t row = (size_t)(bm + h * MH + wid * 32 + lid);
            const uint32_t dbase = tmem + h * 256;
            #pragma unroll
            for (int cb = 0; cb < BN / 32; cb++) {
                uint32_t r[32];
                tc_ld_x32(r, dbase + cb * 32);
                tc_wait_ld();
                float* d0 = C0 + row * (size_t)Ntot + bn + cb * 32;
                if (EPI >= 2) {
                    float* d1 = C1 + row * (size_t)Ntot + bn + cb * 32;
                    __nv_bfloat16* db = (EPI == 3)
                        ? Cb + row * (size_t)(2 * Ntot) + 2 * (size_t)bn + 64 * cb : nullptr;
                    #pragma unroll
                    for (int i = 0; i < 32; i += 4) {
                        float a = __uint_as_float(r[i]),   b = __uint_as_float(r[i+1]);
                        float c = __uint_as_float(r[i+2]), d = __uint_as_float(r[i+3]);
                        float ha = f2tf32(a), hb = f2tf32(b), hc = f2tf32(c), hd = f2tf32(d);
                        float la = a - ha, lb = b - hb, lc = c - hc, ld = d - hd;
                        *(float4*)(d0 + i) = make_float4(ha, hb, hc, hd);
                        *(float4*)(d1 + i) = make_float4(f2tf32(la), f2tf32(lb),
                                                         f2tf32(lc), f2tf32(ld));
                        if (EPI == 3) {
                            int base = 32 * (i >> 4) + (i & 15);
                            db[base + 0]  = __float2bfloat16(a);
                            db[base + 1]  = __float2bfloat16(b);
                            db[base + 2]  = __float2bfloat16(c);
                            db[base + 3]  = __float2bfloat16(d);
                            float bha = __bfloat162float(__float2bfloat16(a));
                            float bhb = __bfloat162float(__float2bfloat16(b));
                            float bhc = __bfloat162float(__float2bfloat16(c));
                            float bhd = __bfloat162float(__float2bfloat16(d));
                            db[base + 16] = __float2bfloat16(a - bha);
                            db[base + 17] = __float2bfloat16(b - bhb);
                            db[base + 18] = __float2bfloat16(c - bhc);
                            db[base + 19] = __float2bfloat16(d - bhd);
                        }
                    }
                } else {
                    #pragma unroll
                    for (int i = 0; i < 32; i += 4) {
                        float a = __uint_as_float(r[i]),   b = __uint_as_float(r[i+1]);
                        float c = __uint_as_float(r[i+2]), d = __uint_as_float(r[i+3]);
                        if (EPI == 1) { a = f2tf32(a); b = f2tf32(b); c = f2tf32(c); d = f2tf32(d); }
                        *(float4*)(d0 + i) = make_float4(a, b, c, d);
                    }
                }
            }
        }
    }
    __syncthreads();
    if (wid == 0) tc_dealloc(tmem, 512);

#else
    // ============== mma.sync fallback (compile-only; sm_103a cubin runs).
    // NMMA 2 and 3 both -> 3x tf32 on the fp32 hi/lo pointers. =============
    constexpr bool THREE = (NMMA != 1);
    constexpr int BKF = 32;
    constexpr int AST = BKF + 4;
    constexpr int A_ELEMS = 128 * AST;
    constexpr int B_ELEMS = 128 * AST;
    constexpr int STAGE = THREE ? 2 * (A_ELEMS + B_ELEMS) : (A_ELEMS + B_ELEMS);
    const int NTF = Ktot / BKF;

    const int lane = tid & 31;
    const int warp = tid >> 5;
    const int wm = (warp & 1) * 64;
    const int wn = (warp >> 1) * 32;
    const int g  = lane >> 2;
    const int t4 = lane & 3;
    const int ar = tid >> 3;
    const int ac = (tid & 7) * 4;

    for (int mh = 0; mh < 2; mh++) {
        const int bm2 = bm + mh * 128;
        for (int nh = 0; nh < 2; nh++) {
            const int bn2 = bn + nh * 128;

            float acc[4][4][4];
            #pragma unroll
            for (int mt = 0; mt < 4; mt++)
                #pragma unroll
                for (int nt = 0; nt < 4; nt++)
                    #pragma unroll
                    for (int i = 0; i < 4; i++) acc[mt][nt][i] = 0.f;

            auto issue_tile = [&](int it, int buf) {
                const int k0 = it * BKF;
                float* a_h = smem + buf * STAGE;
                float* a_l = a_h + A_ELEMS;
                float* b_h = THREE ? a_l + A_ELEMS : a_h + A_ELEMS;
                float* b_l = b_h + B_ELEMS;
                #pragma unroll
                for (int p = 0; p < 4; p++) {
                    int r = ar + p * 32;
                    size_t off = (size_t)(bm2 + r) * Ktot + k0 + ac;
                    cp_async16(&a_h[r * AST + ac], Ah + off);
                    if (THREE) cp_async16(&a_l[r * AST + ac], Al + off);
                }
                #pragma unroll
                for (int p = 0; p < 4; p++) {
                    int n = ar + p * 32;
                    size_t off = (size_t)(bn2 + n) * Ktot + k0 + ac;
                    cp_async16(&b_h[n * AST + ac], Bh + off);
                    if (THREE) cp_async16(&b_l[n * AST + ac], Bl + off);
                }
                cp_commit();
            };

            issue_tile(0, 0);

            for (int it = 0; it < NTF; it++) {
                const bool has_next = (it + 1 < NTF);
                if (has_next) issue_tile(it + 1, (it + 1) & 1);
                if (has_next) cp_wait<1>(); else cp_wait<0>();
                __syncthreads();

                const float* a_h = smem + (it & 1) * STAGE;
                const float* a_l = a_h + A_ELEMS;
                const float* b_h = THREE ? a_l + A_ELEMS : a_h + A_ELEMS;
                const float* b_l = b_h + B_ELEMS;

                #pragma unroll
                for (int kk = 0; kk < 4; kk++) {
                    const int k = kk * 8;
                    uint32_t bh[4][2], bl[4][2];
                    #pragma unroll
                    for (int nt = 0; nt < 4; nt++) {
                        int c = wn + nt * 8 + g;
                        #pragma unroll
                        for (int j = 0; j < 2; j++) {
                            int idx = c * AST + k + 4 * j + t4;
                            bh[nt][j] = __float_as_uint(b_h[idx]);
                            if (THREE) bl[nt][j] = __float_as_uint(b_l[idx]);
                        }
                    }
                    #pragma unroll
                    for (int mt = 0; mt < 4; mt++) {
                        int r0 = wm + mt * 16 + g;
                        int i0 = r0 * AST + k + t4;
                        int i1 = (r0 + 8) * AST + k + t4;
                        uint32_t ah[4], al[4];
                        ah[0] = __float_as_uint(a_h[i0]);     ah[1] = __float_as_uint(a_h[i1]);
                        ah[2] = __float_as_uint(a_h[i0 + 4]); ah[3] = __float_as_uint(a_h[i1 + 4]);
                        if (THREE) {
                            al[0] = __float_as_uint(a_l[i0]);     al[1] = __float_as_uint(a_l[i1]);
                            al[2] = __float_as_uint(a_l[i0 + 4]); al[3] = __float_as_uint(a_l[i1 + 4]);
                        }
                        #pragma unroll
                        for (int nt = 0; nt < 4; nt++) {
                            if (THREE) {
                                mma_sync_tf32(acc[mt][nt], ah, bl[nt]);
                                mma_sync_tf32(acc[mt][nt], al, bh[nt]);
                            }
                            mma_sync_tf32(acc[mt][nt], ah, bh[nt]);
                        }
                    }
                }
                __syncthreads();
            }

            #pragma unroll
            for (int mt = 0; mt < 4; mt++) {
                #pragma unroll
                for (int nt = 0; nt < 4; nt++) {
                    int m0 = bm2 + wm + mt * 16 + g;
                    int n0 = bn2 + wn + nt * 8 + 2 * t4;
                    size_t o0 = (size_t)m0 * Ntot + n0;
                    size_t o1 = (size_t)(m0 + 8) * Ntot + n0;
                    float v0 = acc[mt][nt][0], v1 = acc[mt][nt][1];
                    float v2 = acc[mt][nt][2], v3 = acc[mt][nt][3];
                    if (EPI >= 2) {
                        float h0 = f2tf32(v0), h1 = f2tf32(v1), h2 = f2tf32(v2), h3 = f2tf32(v3);
                        *(float2*)&C0[o0] = make_float2(h0, h1);
                        *(float2*)&C0[o1] = make_float2(h2, h3);
                        *(float2*)&C1[o0] = make_float2(f2tf32(v0 - h0), f2tf32(v1 - h1));
                        *(float2*)&C1[o1] = make_float2(f2tf32(v2 - h2), f2tf32(v3 - h3));
                    } else {
                        if (EPI == 1) { v0 = f2tf32(v0); v1 = f2tf32(v1); v2 = f2tf32(v2); v3 = f2tf32(v3); }
                        *(float2*)&C0[o0] = make_float2(v0, v1);
                        *(float2*)&C0[o1] = make_float2(v2, v3);
                    }
                }
            }
            __syncthreads();
        }
    }
#endif
}

// ---------------------------------------------------------------------------
// Pre-pass kernels (unchanged from R12)
// ---------------------------------------------------------------------------
template <bool LO>
__global__ void split_kernel(const float* __restrict__ src, float* __restrict__ hi,
                             float* __restrict__ lo, int n4)
{
    int i = blockIdx.x * blockDim.x + threadIdx.x;
    int stride = gridDim.x * blockDim.x;
    for (; i < n4; i += stride) {
        float4 v = ((const float4*)src)[i];
        float4 h = make_float4(f2tf32(v.x), f2tf32(v.y), f2tf32(v.z), f2tf32(v.w));
        ((float4*)hi)[i] = h;
        if (LO) {
            ((float4*)lo)[i] = make_float4(f2tf32(v.x - h.x), f2tf32(v.y - h.y),
                                           f2tf32(v.z - h.z), f2tf32(v.w - h.w));
        }
    }
}

template <bool LO>
__global__ void transpose_split_kernel(const float* __restrict__ src,
                                       float* __restrict__ dh, float* __restrict__ dl,
                                       int R, int C)
{
    __shared__ float t[32][33];
    const int bx = blockIdx.x * 32, by = blockIdx.y * 32;
    const int tx = threadIdx.x, ty = threadIdx.y;    // block (32, 8)
    #pragma unroll
    for (int j = 0; j < 32; j += 8)
        t[ty + j][tx] = src[(size_t)(by + ty + j) * C + bx + tx];
    __syncthreads();
    #pragma unroll
    for (int j = 0; j < 32; j += 8) {
        float v = t[tx][ty + j];
        float h = f2tf32(v);
        size_t o = (size_t)(bx + ty + j) * R + by + tx;
        dh[o] = h;
        if (LO) dl[o] = f2tf32(v - h);
    }
}

// Fast exp for t <= 0 on the FMA/ALU pipes. Rel err ~1e-7.
__device__ __forceinline__ float exp_fma(float t) {
    float r = t * 1.4426950408889634f;
    r = fmaxf(r, -125.0f);
    float rr = r + 12582912.0f;
    float ri = rr - 12582912.0f;
    float f = r - ri;
    int   i = (int)ri;
    float p = 1.54035304e-4f;
    p = fmaf(p, f, 1.33335581e-3f);
    p = fmaf(p, f, 9.61812911e-3f);
    p = fmaf(p, f, 5.55041087e-2f);
    p = fmaf(p, f, 2.40226507e-1f);
    p = fmaf(p, f, 6.93147181e-1f);
    p = fmaf(p, f, 1.0f);
    return __int_as_float(__float_as_int(p) + (i << 23));
}

// Row softmax over S [SEQ, SEQ] in place, scale 1/32 fused; output tf32-rounded.
__global__ __launch_bounds__(256)
void softmax_rows_kernel(float* __restrict__ S)
{
    const int row = blockIdx.x;
    float4* p = (float4*)(S + (size_t)row * SEQ);
    const int tid = threadIdx.x;

    float4 v[8];
    float m = -1e30f;
    #pragma unroll
    for (int j = 0; j < 8; j++) {
        v[j] = p[tid + j * 256];
        m = fmaxf(m, fmaxf(fmaxf(v[j].x, v[j].y), fmaxf(v[j].z, v[j].w)));
    }
    __shared__ float redm[8], reds[8];
    #pragma unroll
    for (int o = 16; o; o >>= 1) m = fmaxf(m, __shfl_xor_sync(0xffffffffu, m, o));
    if ((tid & 31) == 0) redm[tid >> 5] = m;
    __syncthreads();
    float bm = redm[0];
    #pragma unroll
    for (int i = 1; i < 8; i++) bm = fmaxf(bm, redm[i]);

    const float SC = 0.03125f;  // 1/sqrt(1024)
    float s = 0.f;
    #pragma unroll
    for (int j = 0; j < 8; j++) {
        v[j].x = __expf((v[j].x - bm) * SC);
        v[j].y = __expf((v[j].y - bm) * SC);
        v[j].z = __expf((v[j].z - bm) * SC);
        v[j].w = exp_fma((v[j].w - bm) * SC);
        s += (v[j].x + v[j].y) + (v[j].z + v[j].w);
    }
    #pragma unroll
    for (int o = 16; o; o >>= 1) s += __shfl_xor_sync(0xffffffffu, s, o);
    if ((tid & 31) == 0) reds[tid >> 5] = s;
    __syncthreads();
    float tot = 0.f;
    #pragma unroll
    for (int i = 0; i < 8; i++) tot += reds[i];
    const float r = 1.f / tot;

    #pragma unroll
    for (int j = 0; j < 8; j++) {
        v[j].x = f2tf32(v[j].x * r); v[j].y = f2tf32(v[j].y * r);
        v[j].z = f2tf32(v[j].z * r); v[j].w = f2tf32(v[j].w * r);
        p[tid + j * 256] = v[j];
    }
}

// ---------------------------------------------------------------------------
// Host
// ---------------------------------------------------------------------------
typedef CUresult (*PFN_tmapenc)(CUtensorMap*, CUtensorMapDataType, cuuint32_t, void*,
                                const cuuint64_t*, const cuuint64_t*, const cuuint32_t*,
                                const cuuint32_t*, CUtensorMapInterleave, CUtensorMapSwizzle,
                                CUtensorMapL2promotion, CUtensorMapFloatOOBfill);

static void build_map_f32(PFN_tmapenc enc, CUtensorMap* m, float* p,
                          uint64_t rows, uint64_t cols)
{
    cuuint64_t dims[3] = {cols, rows, 1};
    cuuint64_t strides[2] = {cols * 4, rows * cols * 4};
    cuuint32_t box[3] = {16, 256, 1};   // 16 f32 = 64 B rows (SW64)
    cuuint32_t es[3] = {1, 1, 1};
    if (enc)
        enc(m, CU_TENSOR_MAP_DATA_TYPE_FLOAT32, 3, p, dims, strides, box, es,
            CU_TENSOR_MAP_INTERLEAVE_NONE, CU_TENSOR_MAP_SWIZZLE_64B,
            CU_TENSOR_MAP_L2_PROMOTION_L2_128B, CU_TENSOR_MAP_FLOAT_OOB_FILL_NONE);
}
static void build_map_bf16(PFN_tmapenc enc, CUtensorMap* m, __nv_bfloat16* p,
                           uint64_t rows, uint64_t cols2)
{
    cuuint64_t dims[3] = {cols2, rows, 1};
    cuuint64_t strides[2] = {cols2 * 2, rows * cols2 * 2};
    cuuint32_t box[3] = {32, 256, 1};   // 32 bf16 = 64 B rows (SW64)
    cuuint32_t es[3] = {1, 1, 1};
    if (enc)
        enc(m, CU_TENSOR_MAP_DATA_TYPE_BFLOAT16, 3, p, dims, strides, box, es,
            CU_TENSOR_MAP_INTERLEAVE_NONE, CU_TENSOR_MAP_SWIZZLE_64B,
            CU_TENSOR_MAP_L2_PROMOTION_L2_128B, CU_TENSOR_MAP_FLOAT_OOB_FILL_NONE);
}

extern "C" void kernel_launch(void* const* d_in, const int* in_sizes, int n_in,
                              void* d_out, int out_size)
{
    const float* x = nullptr;
    const float* w[3] = {nullptr, nullptr, nullptr};
    int wi = 0;
    for (int i = 0; i < n_in; i++) {
        if (in_sizes[i] == SEQ * DIM && x == nullptr) x = (const float*)d_in[i];
        else if (wi < 3) w[wi++] = (const float*)d_in[i];
    }
    float* out = (float*)d_out;

    float *xh, *xl, *wqth, *wqtl, *wkth, *wktl, *wvt;
    float *qh, *ql, *kh, *kl, *vt, *s;
    __nv_bfloat16 *qb, *kb;
    cudaGetSymbolAddress((void**)&xh, g_xh);     cudaGetSymbolAddress((void**)&xl, g_xl);
    cudaGetSymbolAddress((void**)&wqth, g_wqth); cudaGetSymbolAddress((void**)&wqtl, g_wqtl);
    cudaGetSymbolAddress((void**)&wkth, g_wkth); cudaGetSymbolAddress((void**)&wktl, g_wktl);
    cudaGetSymbolAddress((void**)&wvt, g_wvt);
    cudaGetSymbolAddress((void**)&qh, g_qh);     cudaGetSymbolAddress((void**)&ql, g_ql);
    cudaGetSymbolAddress((void**)&qb, g_qb);
    cudaGetSymbolAddress((void**)&kh, g_kh);     cudaGetSymbolAddress((void**)&kl, g_kl);
    cudaGetSymbolAddress((void**)&kb, g_kb);
    cudaGetSymbolAddress((void**)&vt, g_vt);     cudaGetSymbolAddress((void**)&s, g_s);

    void* pfn = nullptr;
    cudaDriverEntryPointQueryResult qr;
    cudaGetDriverEntryPoint("cuTensorMapEncodeTiled", &pfn, cudaEnableDefault, &qr);
    PFN_tmapenc enc = (PFN_tmapenc)pfn;

    CUtensorMap m_xh, m_xl, m_wqth, m_wqtl, m_wkth, m_wktl, m_wvt;
    CUtensorMap m_qb, m_kb, m_vt, m_s;
    build_map_f32(enc, &m_xh, xh, SEQ, DIM);     build_map_f32(enc, &m_xl, xl, SEQ, DIM);
    build_map_f32(enc, &m_wqth, wqth, DIM, DIM); build_map_f32(enc, &m_wqtl, wqtl, DIM, DIM);
    build_map_f32(enc, &m_wkth, wkth, DIM, DIM); build_map_f32(enc, &m_wktl, wktl, DIM, DIM);
    build_map_f32(enc, &m_wvt, wvt, DIM, DIM);
    build_map_bf16(enc, &m_qb, qb, SEQ, 2 * DIM);
    build_map_bf16(enc, &m_kb, kb, SEQ, 2 * DIM);
    build_map_f32(enc, &m_vt, vt, DIM, SEQ);
    build_map_f32(enc, &m_s, s, SEQ, SEQ);

    // smem: NMMA3 = 3x64KB; NMMA1/2 = 3x32KB (+1KB align). Covers fallback.
    const int smem3 = 3 * 4 * 16384 + 1024;   // 197,632
    const int smem1 = 3 * 2 * 16384 + 1024;   //  99,328
    cudaFuncSetAttribute(tc_gemm<3, 3>, cudaFuncAttributeMaxDynamicSharedMemorySize, smem3);
    cudaFuncSetAttribute(tc_gemm<2, 0>, cudaFuncAttributeMaxDynamicSharedMemorySize,
                         3 * 2 * (128 * 36 + 128 * 36) * 4);  // fallback needs 147,456
    cudaFuncSetAttribute(tc_gemm<1, 1>, cudaFuncAttributeMaxDynamicSharedMemorySize, smem1);
    cudaFuncSetAttribute(tc_gemm<1, 0>, cudaFuncAttributeMaxDynamicSharedMemorySize, smem1);

    // --- pre-pass (unchanged) ---
    split_kernel<true><<<512, 256>>>(x, xh, xl, SEQ * DIM / 4);
    dim3 tb(32, 8), tg(DIM / 32, DIM / 32);
    transpose_split_kernel<true><<<tg, tb>>>(w[0], wqth, wqtl, DIM, DIM);
    transpose_split_kernel<true><<<tg, tb>>>(w[1], wkth, wktl, DIM, DIM);
    transpose_split_kernel<false><<<tg, tb>>>(w[2], wvt, nullptr, DIM, DIM);

    // --- Q, K projections (tf32 3-term; EPI=3 adds bf16 interleaved out) ---
    dim3 gproj(DIM / BN, SEQ / BM);   // (4, 32)
    tc_gemm<3, 3><<<gproj, 256, smem3>>>(m_xh, m_xl, m_wqth, m_wqtl,
                                         xh, xl, wqth, wqtl, qh, ql, qb, DIM, DIM);
    tc_gemm<3, 3><<<gproj, 256, smem3>>>(m_xh, m_xl, m_wkth, m_wktl,
                                         xh, xl, wkth, wktl, kh, kl, kb, DIM, DIM);

    // --- V^T = Wv^T @ X^T (tf32 1x, tf32-rounded out): C[DIM, SEQ] ---
    dim3 gvt(SEQ / BN, DIM / BM);     // (32, 4)
    tc_gemm<1, 1><<<gvt, 256, smem1>>>(m_wvt, m_wvt, m_xh, m_xh,
                                       wvt, wvt, xh, xh, vt, nullptr, nullptr, SEQ, DIM);

    // --- S = Q @ K^T (PURE bf16 3-term — traffic AND MMAs halved) ---
    dim3 gscore(SEQ / BN, SEQ / BM);  // (32, 32)
    const int smemB = 3 * 2 * (128 * 36 + 128 * 36) * 4;   // >= tc 99,328
    tc_gemm<2, 0><<<gscore, 256, smemB>>>(m_qb, m_qb, m_kb, m_kb,
                                          qh, ql, kh, kl, s, nullptr, nullptr, SEQ, DIM);

    softmax_rows_kernel<<<SEQ, 256>>>(s);

    // --- out = P @ (V^T)^T (tf32 1x): C[SEQ, DIM] ---
    dim3 gpv(DIM / BN, SEQ / BM);     // (4, 32)
    tc_gemm<1, 0><<<gpv, 256, smem1>>>(m_s, m_s, m_vt, m_vt,
                                       s, s, vt, vt, out, nullptr, nullptr, DIM, SEQ);
}

// round 14
// speedup vs baseline: 1.3197x; 1.3197x over previous
#include <cuda_runtime.h>
#include <cuda.h>
#include <cuda_bf16.h>
#include <cstdint>

#define SEQ 8192
#define DIM 1024

// tcgen05 is only legal when compiling the arch-specific (sm_103a) device pass.
#if (defined(__CUDA_ARCH_FEAT_SM103_ALL) || (defined(__CUDA_ARCH_SPECIFIC__) && (__CUDA_ARCH_SPECIFIC__ == 1030)))
#define TC_PATH 1
#else
#define TC_PATH 0
#endif

// ---- device scratch (no allocations allowed) ----
__device__ float g_xh[SEQ * DIM], g_xl[SEQ * DIM];          // x hi/lo fp32 (k-major)
__device__ float g_wqth[DIM * DIM], g_wqtl[DIM * DIM];      // Wq^T hi/lo
__device__ float g_wkth[DIM * DIM], g_wktl[DIM * DIM];      // Wk^T hi/lo
__device__ float g_wvt[DIM * DIM];                          // Wv^T (tf32)
__device__ float g_qh[SEQ * DIM], g_ql[SEQ * DIM];          // Q hi/lo fp32 (fallback only)
__device__ __nv_bfloat16 g_qb[SEQ * 2 * DIM];               // Q bf16 interleaved [hi16|lo16]
__device__ float g_kh[SEQ * DIM], g_kl[SEQ * DIM];          // K hi/lo fp32 (fallback only)
__device__ __nv_bfloat16 g_kb[SEQ * 2 * DIM];               // K bf16 interleaved
__device__ float g_vt[(size_t)DIM * SEQ];                   // V^T (tf32) [DIM, SEQ]
__device__ float g_s[(size_t)SEQ * SEQ];                    // scores / weights

// ---------------------------------------------------------------------------
// Common helpers
// ---------------------------------------------------------------------------
__device__ __forceinline__ float f2tf32(float f) {
    uint32_t r;
    asm("cvt.rna.tf32.f32 %0, %1;" : "=r"(r) : "f"(f));
    return __uint_as_float(r);
}
__device__ __forceinline__ uint32_t smem_u32(const void* p) {
    uint32_t a;
    asm("{ .reg .u64 t; cvta.to.shared.u64 t, %1; cvt.u32.u64 %0, t; }" : "=r"(a) : "l"(p));
    return a;
}
__device__ __forceinline__ void cp_async16(float* smem_dst, const float* gmem_src) {
    uint32_t s = (uint32_t)__cvta_generic_to_shared(smem_dst);
    asm volatile("cp.async.cg.shared.global [%0], [%1], 16;\n" :: "r"(s), "l"(gmem_src));
}
__device__ __forceinline__ void cp_commit() { asm volatile("cp.async.commit_group;\n"); }
template <int N>
__device__ __forceinline__ void cp_wait() { asm volatile("cp.async.wait_group %0;\n" :: "n"(N)); }

__device__ __forceinline__ void mma_sync_tf32(float* d, const uint32_t* a, const uint32_t* b) {
    asm volatile(
        "mma.sync.aligned.m16n8k8.row.col.f32.tf32.tf32.f32 "
        "{%0,%1,%2,%3}, {%4,%5,%6,%7}, {%8,%9}, {%0,%1,%2,%3};\n"
        : "+f"(d[0]), "+f"(d[1]), "+f"(d[2]), "+f"(d[3])
        : "r"(a[0]), "r"(a[1]), "r"(a[2]), "r"(a[3]), "r"(b[0]), "r"(b[1]));
}

// ---------------------------------------------------------------------------
// mbarrier / TMA helpers
// ---------------------------------------------------------------------------
__device__ __forceinline__ void mbar_init(uint32_t a, uint32_t cnt) {
    asm volatile("mbarrier.init.shared.b64 [%0], %1;" :: "r"(a), "r"(cnt) : "memory");
}
__device__ __forceinline__ void mbar_expect(uint32_t a, uint32_t bytes) {
    asm volatile("mbarrier.arrive.expect_tx.shared.b64 _, [%0], %1;" :: "r"(a), "r"(bytes) : "memory");
}
__device__ __forceinline__ void mbar_wait(uint32_t a, uint32_t parity) {
    asm volatile(
        "{\n\t"
        ".reg .pred P1;\n\t"
        "LAB_WAIT%=:\n\t"
        "mbarrier.try_wait.parity.acquire.cta.shared::cta.b64 P1, [%0], %1, 0x989680;\n\t"
        "@P1 bra LAB_DONE%=;\n\t"
        "bra LAB_WAIT%=;\n\t"
        "LAB_DONE%=:\n\t"
        "}"
        :: "r"(a), "r"(parity) : "memory");
}
__device__ __forceinline__ void tma3d(uint32_t dst, const CUtensorMap* m, int x, int y, uint32_t mbar) {
    asm volatile(
        "cp.async.bulk.tensor.3d.shared::cta.global.tile.mbarrier::complete_tx::bytes "
        "[%0], [%1, {%2, %3, %4}], [%5];"
        :: "r"(dst), "l"(m), "r"(x), "r"(y), "r"(0), "r"(mbar) : "memory");
}
#if TC_PATH
__device__ __forceinline__ void tc_alloc(uint32_t smem_result, uint32_t ncols) {
    asm volatile("tcgen05.alloc.cta_group::1.sync.aligned.shared::cta.b32 [%0], %1;"
                 :: "r"(smem_result), "r"(ncols) : "memory");
}
__device__ __forceinline__ void tc_dealloc(uint32_t tmem, uint32_t ncols) {
    asm volatile("tcgen05.dealloc.cta_group::1.sync.aligned.b32 %0, %1;" :: "r"(tmem), "r"(ncols));
}
__device__ __forceinline__ void tc_commit(uint32_t mbar) {
    asm volatile("tcgen05.commit.cta_group::1.mbarrier::arrive::one.shared::cluster.b64 [%0];"
                 :: "r"(mbar) : "memory");
}
__device__ __forceinline__ void tc_fence_after() {
    asm volatile("tcgen05.fence::after_thread_sync;" ::: "memory");
}
__device__ __forceinline__ void tc_wait_ld() {
    asm volatile("tcgen05.wait::ld.sync.aligned;" ::: "memory");
}
__device__ __forceinline__ void tc_ld_x32(uint32_t* r, uint32_t tmem) {
    asm volatile(
        "tcgen05.ld.sync.aligned.32x32b.x32.b32 "
        "{%0, %1, %2, %3, %4, %5, %6, %7, %8, %9, %10, %11, %12, %13, %14, %15, "
        " %16, %17, %18, %19, %20, %21, %22, %23, %24, %25, %26, %27, %28, %29, %30, %31}, [%32];"
        : "=r"(r[0]), "=r"(r[1]), "=r"(r[2]), "=r"(r[3]), "=r"(r[4]), "=r"(r[5]), "=r"(r[6]), "=r"(r[7]),
          "=r"(r[8]), "=r"(r[9]), "=r"(r[10]), "=r"(r[11]), "=r"(r[12]), "=r"(r[13]), "=r"(r[14]), "=r"(r[15]),
          "=r"(r[16]), "=r"(r[17]), "=r"(r[18]), "=r"(r[19]), "=r"(r[20]), "=r"(r[21]), "=r"(r[22]), "=r"(r[23]),
          "=r"(r[24]), "=r"(r[25]), "=r"(r[26]), "=r"(r[27]), "=r"(r[28]), "=r"(r[29]), "=r"(r[30]), "=r"(r[31])
        : "r"(tmem));
}
__device__ __forceinline__ void mma_ss_tf32(uint32_t d, uint64_t a, uint64_t b, uint32_t idesc, uint32_t en) {
    asm volatile(
        "{\n\t"
        ".reg .pred p;\n\t"
        "setp.ne.u32 p, %4, 0;\n\t"
        "tcgen05.mma.cta_group::1.kind::tf32 [%0], %1, %2, %3, {%5, %5, %5, %5}, p;\n\t"
        "}"
        :: "r"(d), "l"(a), "l"(b), "r"(idesc), "r"(en), "r"(0u) : "memory");
}
__device__ __forceinline__ void mma_ss_bf16(uint32_t d, uint64_t a, uint64_t b, uint32_t idesc, uint32_t en) {
    asm volatile(
        "{\n\t"
        ".reg .pred p;\n\t"
        "setp.ne.u32 p, %4, 0;\n\t"
        "tcgen05.mma.cta_group::1.kind::f16 [%0], %1, %2, %3, {%5, %5, %5, %5}, p;\n\t"
        "}"
        :: "r"(d), "l"(a), "l"(b), "r"(idesc), "r"(en), "r"(0u) : "memory");
}
#endif

// SW64 smem descriptor (64B rows): layout=SW64(4), version=1, SBO=32, LBO=1
static constexpr uint64_t DESC_BASE_SW64 =
    (4ull << 61) | (1ull << 46) | (32ull << 32) | (1ull << 16);
__device__ __forceinline__ uint64_t make_desc64(uint32_t addr) {
    return DESC_BASE_SW64 | ((uint64_t)(addr >> 4) & 0x3FFF);
}
// SW128 smem descriptor (128B rows): layout=SW128(2), version=1, SBO=64, LBO=1
static constexpr uint64_t DESC_BASE_SW128 =
    (2ull << 61) | (1ull << 46) | (64ull << 32) | (1ull << 16);
__device__ __forceinline__ uint64_t make_desc128(uint32_t addr) {
    return DESC_BASE_SW128 | ((uint64_t)(addr >> 4) & 0x3FFF);
}

// ---------------------------------------------------------------------------
// Unified GEMM: C[M, Ntot] = A[M, K] * B[Ntot, K]^T.
// NMMA==1: tf32 1x, BK=16, SW64 fp32 tiles.
// NMMA==3: tf32 3-term hi/lo, BK=16, SW64 fp32 hi+lo tiles.
// NMMA==2: bf16 3-term, BK=32, SW128 bf16 interleaved [hi16|lo16] tiles;
//          hi*hi + hi*lo + lo*hi at kind::f16 K=16. Traffic and MMA cycles
//          both halved vs NMMA==3 at the SAME per-chunk granularity (1536 cyc)
//          so driver overhead stays amortized (the R13 lesson).
// CTA tile 256x256 (two M=128 halves -> TMEM 512 cols), 3-stage TMA pipeline
// with deferred done-waits (R12), 256 threads, no clusters.
// EPI: 0=raw, 1=tf32-rounded, 2=fp32 hi/lo split,
//      4=bf16 interleaved ONLY (TC path; fallback writes fp32 hi/lo).
// ---------------------------------------------------------------------------
constexpr int BM = 256, BN = 256;
constexpr int MH = 128;
constexpr uint32_t IDESC_TF32 =
    (1u << 4) | (2u << 7) | (2u << 10) | ((BN / 8) << 17) | ((MH / 16) << 24);
constexpr uint32_t IDESC_BF16 =
    (1u << 4) | (1u << 7) | (1u << 10) | ((BN / 8) << 17) | ((MH / 16) << 24);

template <int NMMA, int EPI>
__global__ __launch_bounds__(256, 1)
void tc_gemm(const __grid_constant__ CUtensorMap tmA0,
             const __grid_constant__ CUtensorMap tmA1,
             const __grid_constant__ CUtensorMap tmB0,
             const __grid_constant__ CUtensorMap tmB1,
             const float* __restrict__ Ah, const float* __restrict__ Al,
             const float* __restrict__ Bh, const float* __restrict__ Bl,
             float* __restrict__ C0, float* __restrict__ C1,
             __nv_bfloat16* __restrict__ Cb,
             int Ntot, int Ktot)
{
    extern __shared__ __align__(16) float smem[];
    const int tid = threadIdx.x;
    const int bn = blockIdx.x * BN;
    const int bm = blockIdx.y * BM;

#if TC_PATH
    // ======================= tcgen05 + TMA path =======================
    constexpr int BK = (NMMA == 2) ? 32 : 16;               // logical K per chunk
    constexpr int T_BYTES = (NMMA == 2) ? 32768 : 16384;    // per-operand tile
    constexpr int NTILE = (NMMA == 3) ? 4 : 2;
    constexpr int STAGE = (NMMA == 3) ? 4 * 16384 : NTILE * T_BYTES;
    constexpr int NS = 3;
    constexpr uint32_t AH1 = (NMMA == 2) ? 1024 : 512;      // A M-half-1 offset (16B units)
    const int NT = Ktot / BK;

    __shared__ __align__(8) uint64_t mbar_store[2 * NS];
    __shared__ uint32_t tmem_ptr;

    const int wid = tid >> 5;
    const int lid = tid & 31;
    const uint32_t sbase = (smem_u32(smem) + 1023) & ~1023u;
    uint32_t mb_full[NS], mb_done[NS];
    #pragma unroll
    for (int s = 0; s < NS; s++) {
        mb_full[s] = smem_u32(&mbar_store[s]);
        mb_done[s] = smem_u32(&mbar_store[NS + s]);
    }

    if (wid == 0) tc_alloc(smem_u32(&tmem_ptr), 512);
    if (tid == 0) {
        #pragma unroll
        for (int s = 0; s < NS; s++) { mbar_init(mb_full[s], 1); mbar_init(mb_done[s], 1); }
    }
    __syncthreads();
    const uint32_t tmem = tmem_ptr;      // D0 = cols 0-255, D1 = cols 256-511

    if (tid == 0) {
        uint32_t pf[NS] = {};
        const uint32_t boff = (NMMA == 3) ? 2 * 16384 : T_BYTES;

        auto issue = [&](int it, int s) {
            const uint32_t st = sbase + (uint32_t)s * STAGE;
            const int k0 = it * BK;
            mbar_expect(mb_full[s], (uint32_t)STAGE);
            if (NMMA == 2) {
                tma3d(st,        &tmA0, 2 * k0, bm, mb_full[s]);   // bf16 x = 2*k
                tma3d(st + boff, &tmB0, 2 * k0, bn, mb_full[s]);
            } else {
                tma3d(st, &tmA0, k0, bm, mb_full[s]);
                if (NMMA == 3) tma3d(st + 16384, &tmA1, k0, bm, mb_full[s]);
                tma3d(st + boff, &tmB0, k0, bn, mb_full[s]);
                if (NMMA == 3) tma3d(st + boff + 16384, &tmB1, k0, bn, mb_full[s]);
            }
        };

        #pragma unroll
        for (int s = 0; s < NS; s++)
            if (s < NT) issue(s, s);

        for (int it = 0; it < NT; it++) {
            const int s = it % NS;
            mbar_wait(mb_full[s], pf[s]); pf[s] ^= 1;

            const uint32_t st = sbase + (uint32_t)s * STAGE;

            if (NMMA == 2) {
                // SW128 bf16: row = 128 B = two 16-K groups {hi,lo} at 16B-units
                // {0,2,4,6}. 12 MMAs of K=16 per chunk (3 terms x 2 groups x 2 halves).
                const uint64_t da = make_desc128(st);
                const uint64_t db = make_desc128(st + boff);
                #pragma unroll
                for (int ks = 0; ks < 2; ks++) {
                    const uint64_t o = 4 * ks;
                    const uint32_t en0 = (it > 0 || ks > 0) ? 1u : 0u;
                    #pragma unroll
                    for (int h = 0; h < 2; h++) {
                        const uint32_t d = tmem + h * 256;
                        const uint64_t ha = h * (uint64_t)AH1;
                        mma_ss_bf16(d, da + ha + o,     db + o,     IDESC_BF16, en0); // hi*hi
                        mma_ss_bf16(d, da + ha + o,     db + o + 2, IDESC_BF16, 1u);  // hi*lo
                        mma_ss_bf16(d, da + ha + o + 2, db + o,     IDESC_BF16, 1u);  // lo*hi
                    }
                }
            } else {
                const uint64_t da0 = make_desc64(st);
                const uint64_t db0 = make_desc64(st + boff);
                const uint64_t da1 = make_desc64(st + 16384);
                const uint64_t db1 = make_desc64(st + boff + 16384);
                #pragma unroll
                for (int ks = 0; ks < 2; ks++) {            // two K=8 steps
                    const uint64_t o = 2 * ks;
                    const uint32_t en0 = (it > 0 || ks > 0) ? 1u : 0u;
                    #pragma unroll
                    for (int h = 0; h < 2; h++) {
                        const uint32_t d = tmem + h * 256;
                        const uint64_t ha = h * (uint64_t)AH1;
                        if (NMMA == 3) {
                            mma_ss_tf32(d, da0 + ha + o, db1 + o, IDESC_TF32, en0);
                            mma_ss_tf32(d, da1 + ha + o, db0 + o, IDESC_TF32, 1u);
                            mma_ss_tf32(d, da0 + ha + o, db0 + o, IDESC_TF32, 1u);
                        } else {
                            mma_ss_tf32(d, da0 + ha + o, db0 + o, IDESC_TF32, en0);
                        }
                    }
                }
            }
            tc_commit(mb_done[s]);

            // Deferred refill (R12): current chunk's MMAs already queued keep
            // the tensor pipe busy while we wait on the PREVIOUS chunk.
            const int prev = it - 1;
            if (prev >= 0 && prev + NS < NT) {
                const int sp = prev % NS;
                mbar_wait(mb_done[sp], (uint32_t)((prev / NS) & 1));
                issue(prev + NS, sp);
            }
        }
        mbar_wait(mb_done[(NT - 1) % NS], (uint32_t)(((NT - 1) / NS) & 1));
    }
    __syncthreads();
    tc_fence_after();

    // epilogue: warps 0-3; each D half is 128 rows x 256 cols fp32
    if (wid < 4) {
        #pragma unroll
        for (int h = 0; h < 2; h++) {
            const size_t row = (size_t)(bm + h * MH + wid * 32 + lid);
            const uint32_t dbase = tmem + h * 256;
            #pragma unroll
            for (int cb = 0; cb < BN / 32; cb++) {
                uint32_t r[32];
                tc_ld_x32(r, dbase + cb * 32);
                tc_wait_ld();
                if (EPI == 4) {
                    // bf16 interleaved ONLY: [hi16|lo16] per 16-col group, packed
                    // 4-byte stores.
                    __nv_bfloat16* db = Cb + row * (size_t)(2 * Ntot) + 2 * (size_t)bn + 64 * cb;
                    #pragma unroll
                    for (int i = 0; i < 32; i += 4) {
                        float a = __uint_as_float(r[i]),   b = __uint_as_float(r[i+1]);
                        float c = __uint_as_float(r[i+2]), d = __uint_as_float(r[i+3]);
                        __nv_bfloat162 h01 = __floats2bfloat162_rn(a, b);
                        __nv_bfloat162 h23 = __floats2bfloat162_rn(c, d);
                        float la = a - __bfloat162float(h01.x);
                        float lb = b - __bfloat162float(h01.y);
                        float lc = c - __bfloat162float(h23.x);
                        float ld = d - __bfloat162float(h23.y);
                        int base = 32 * (i >> 4) + (i & 15);
                        *(__nv_bfloat162*)(db + base)      = h01;
                        *(__nv_bfloat162*)(db + base + 2)  = h23;
                        *(__nv_bfloat162*)(db + base + 16) = __floats2bfloat162_rn(la, lb);
                        *(__nv_bfloat162*)(db + base + 18) = __floats2bfloat162_rn(lc, ld);
                    }
                } else {
                    float* d0 = C0 + row * (size_t)Ntot + bn + cb * 32;
                    if (EPI == 2) {
                        float* d1 = C1 + row * (size_t)Ntot + bn + cb * 32;
                        #pragma unroll
                        for (int i = 0; i < 32; i += 4) {
                            float a = __uint_as_float(r[i]),   b = __uint_as_float(r[i+1]);
                            float c = __uint_as_float(r[i+2]), d = __uint_as_float(r[i+3]);
                            float ha = f2tf32(a), hb = f2tf32(b), hc = f2tf32(c), hd = f2tf32(d);
                            *(float4*)(d0 + i) = make_float4(ha, hb, hc, hd);
                            *(float4*)(d1 + i) = make_float4(f2tf32(a - ha), f2tf32(b - hb),
                                                             f2tf32(c - hc), f2tf32(d - hd));
                        }
                    } else {
                        #pragma unroll
                        for (int i = 0; i < 32; i += 4) {
                            float a = __uint_as_float(r[i]),   b = __uint_as_float(r[i+1]);
                            float c = __uint_as_float(r[i+2]), d = __uint_as_float(r[i+3]);
                            if (EPI == 1) { a = f2tf32(a); b = f2tf32(b); c = f2tf32(c); d = f2tf32(d); }
                            *(float4*)(d0 + i) = make_float4(a, b, c, d);
                        }
                    }
                }
            }
        }
    }
    __syncthreads();
    if (wid == 0) tc_dealloc(tmem, 512);

#else
    // ============== mma.sync fallback (compile-only; sm_103a cubin runs).
    // NMMA 2/3 -> 3x tf32 on the fp32 hi/lo pointers; EPI 4 -> fp32 split. ====
    constexpr bool THREE = (NMMA != 1);
    constexpr int BKF = 32;
    constexpr int AST = BKF + 4;
    constexpr int A_ELEMS = 128 * AST;
    constexpr int B_ELEMS = 128 * AST;
    constexpr int STAGE = THREE ? 2 * (A_ELEMS + B_ELEMS) : (A_ELEMS + B_ELEMS);
    const int NTF = Ktot / BKF;

    const int lane = tid & 31;
    const int warp = tid >> 5;
    const int wm = (warp & 1) * 64;
    const int wn = (warp >> 1) * 32;
    const int g  = lane >> 2;
    const int t4 = lane & 3;
    const int ar = tid >> 3;
    const int ac = (tid & 7) * 4;

    for (int mh = 0; mh < 2; mh++) {
        const int bm2 = bm + mh * 128;
        for (int nh = 0; nh < 2; nh++) {
            const int bn2 = bn + nh * 128;

            float acc[4][4][4];
            #pragma unroll
            for (int mt = 0; mt < 4; mt++)
                #pragma unroll
                for (int nt = 0; nt < 4; nt++)
                    #pragma unroll
                    for (int i = 0; i < 4; i++) acc[mt][nt][i] = 0.f;

            auto issue_tile = [&](int it, int buf) {
                const int k0 = it * BKF;
                float* a_h = smem + buf * STAGE;
                float* a_l = a_h + A_ELEMS;
                float* b_h = THREE ? a_l + A_ELEMS : a_h + A_ELEMS;
                float* b_l = b_h + B_ELEMS;
                #pragma unroll
                for (int p = 0; p < 4; p++) {
                    int r = ar + p * 32;
                    size_t off = (size_t)(bm2 + r) * Ktot + k0 + ac;
                    cp_async16(&a_h[r * AST + ac], Ah + off);
                    if (THREE) cp_async16(&a_l[r * AST + ac], Al + off);
                }
                #pragma unroll
                for (int p = 0; p < 4; p++) {
                    int n = ar + p * 32;
                    size_t off = (size_t)(bn2 + n) * Ktot + k0 + ac;
                    cp_async16(&b_h[n * AST + ac], Bh + off);
                    if (THREE) cp_async16(&b_l[n * AST + ac], Bl + off);
                }
                cp_commit();
            };

            issue_tile(0, 0);

            for (int it = 0; it < NTF; it++) {
                const bool has_next = (it + 1 < NTF);
                if (has_next) issue_tile(it + 1, (it + 1) & 1);
                if (has_next) cp_wait<1>(); else cp_wait<0>();
                __syncthreads();

                const float* a_h = smem + (it & 1) * STAGE;
                const float* a_l = a_h + A_ELEMS;
                const float* b_h = THREE ? a_l + A_ELEMS : a_h + A_ELEMS;
                const float* b_l = b_h + B_ELEMS;

                #pragma unroll
                for (int kk = 0; kk < 4; kk++) {
                    const int k = kk * 8;
                    uint32_t bh[4][2], bl[4][2];
                    #pragma unroll
                    for (int nt = 0; nt < 4; nt++) {
                        int c = wn + nt * 8 + g;
                        #pragma unroll
                        for (int j = 0; j < 2; j++) {
                            int idx = c * AST + k + 4 * j + t4;
                            bh[nt][j] = __float_as_uint(b_h[idx]);
                            if (THREE) bl[nt][j] = __float_as_uint(b_l[idx]);
                        }
                    }
                    #pragma unroll
                    for (int mt = 0; mt < 4; mt++) {
                        int r0 = wm + mt * 16 + g;
                        int i0 = r0 * AST + k + t4;
                        int i1 = (r0 + 8) * AST + k + t4;
                        uint32_t ah[4], al[4];
                        ah[0] = __float_as_uint(a_h[i0]);     ah[1] = __float_as_uint(a_h[i1]);
                        ah[2] = __float_as_uint(a_h[i0 + 4]); ah[3] = __float_as_uint(a_h[i1 + 4]);
                        if (THREE) {
                            al[0] = __float_as_uint(a_l[i0]);     al[1] = __float_as_uint(a_l[i1]);
                            al[2] = __float_as_uint(a_l[i0 + 4]); al[3] = __float_as_uint(a_l[i1 + 4]);
                        }
                        #pragma unroll
                        for (int nt = 0; nt < 4; nt++) {
                            if (THREE) {
                                mma_sync_tf32(acc[mt][nt], ah, bl[nt]);
                                mma_sync_tf32(acc[mt][nt], al, bh[nt]);
                            }
                            mma_sync_tf32(acc[mt][nt], ah, bh[nt]);
                        }
                    }
                }
                __syncthreads();
            }

            #pragma unroll
            for (int mt = 0; mt < 4; mt++) {
                #pragma unroll
                for (int nt = 0; nt < 4; nt++) {
                    int m0 = bm2 + wm + mt * 16 + g;
                    int n0 = bn2 + wn + nt * 8 + 2 * t4;
                    size_t o0 = (size_t)m0 * Ntot + n0;
                    size_t o1 = (size_t)(m0 + 8) * Ntot + n0;
                    float v0 = acc[mt][nt][0], v1 = acc[mt][nt][1];
                    float v2 = acc[mt][nt][2], v3 = acc[mt][nt][3];
                    if (EPI >= 2) {
                        float h0 = f2tf32(v0), h1 = f2tf32(v1), h2 = f2tf32(v2), h3 = f2tf32(v3);
                        *(float2*)&C0[o0] = make_float2(h0, h1);
                        *(float2*)&C0[o1] = make_float2(h2, h3);
                        *(float2*)&C1[o0] = make_float2(f2tf32(v0 - h0), f2tf32(v1 - h1));
                        *(float2*)&C1[o1] = make_float2(f2tf32(v2 - h2), f2tf32(v3 - h3));
                    } else {
                        if (EPI == 1) { v0 = f2tf32(v0); v1 = f2tf32(v1); v2 = f2tf32(v2); v3 = f2tf32(v3); }
                        *(float2*)&C0[o0] = make_float2(v0, v1);
                        *(float2*)&C0[o1] = make_float2(v2, v3);
                    }
                }
            }
            __syncthreads();
        }
    }
#endif
}

// ---------------------------------------------------------------------------
// Pre-pass kernels (unchanged from R12)
// ---------------------------------------------------------------------------
template <bool LO>
__global__ void split_kernel(const float* __restrict__ src, float* __restrict__ hi,
                             float* __restrict__ lo, int n4)
{
    int i = blockIdx.x * blockDim.x + threadIdx.x;
    int stride = gridDim.x * blockDim.x;
    for (; i < n4; i += stride) {
        float4 v = ((const float4*)src)[i];
        float4 h = make_float4(f2tf32(v.x), f2tf32(v.y), f2tf32(v.z), f2tf32(v.w));
        ((float4*)hi)[i] = h;
        if (LO) {
            ((float4*)lo)[i] = make_float4(f2tf32(v.x - h.x), f2tf32(v.y - h.y),
                                           f2tf32(v.z - h.z), f2tf32(v.w - h.w));
        }
    }
}

template <bool LO>
__global__ void transpose_split_kernel(const float* __restrict__ src,
                                       float* __restrict__ dh, float* __restrict__ dl,
                                       int R, int C)
{
    __shared__ float t[32][33];
    const int bx = blockIdx.x * 32, by = blockIdx.y * 32;
    const int tx = threadIdx.x, ty = threadIdx.y;    // block (32, 8)
    #pragma unroll
    for (int j = 0; j < 32; j += 8)
        t[ty + j][tx] = src[(size_t)(by + ty + j) * C + bx + tx];
    __syncthreads();
    #pragma unroll
    for (int j = 0; j < 32; j += 8) {
        float v = t[tx][ty + j];
        float h = f2tf32(v);
        size_t o = (size_t)(bx + ty + j) * R + by + tx;
        dh[o] = h;
        if (LO) dl[o] = f2tf32(v - h);
    }
}

// Fast exp for t <= 0 on the FMA/ALU pipes. Rel err ~1e-7.
__device__ __forceinline__ float exp_fma(float t) {
    float r = t * 1.4426950408889634f;
    r = fmaxf(r, -125.0f);
    float rr = r + 12582912.0f;
    float ri = rr - 12582912.0f;
    float f = r - ri;
    int   i = (int)ri;
    float p = 1.54035304e-4f;
    p = fmaf(p, f, 1.33335581e-3f);
    p = fmaf(p, f, 9.61812911e-3f);
    p = fmaf(p, f, 5.55041087e-2f);
    p = fmaf(p, f, 2.40226507e-1f);
    p = fmaf(p, f, 6.93147181e-1f);
    p = fmaf(p, f, 1.0f);
    return __int_as_float(__float_as_int(p) + (i << 23));
}

// Row softmax over S [SEQ, SEQ] in place, scale 1/32 fused; output tf32-rounded.
__global__ __launch_bounds__(256)
void softmax_rows_kernel(float* __restrict__ S)
{
    const int row = blockIdx.x;
    float4* p = (float4*)(S + (size_t)row * SEQ);
    const int tid = threadIdx.x;

    float4 v[8];
    float m = -1e30f;
    #pragma unroll
    for (int j = 0; j < 8; j++) {
        v[j] = p[tid + j * 256];
        m = fmaxf(m, fmaxf(fmaxf(v[j].x, v[j].y), fmaxf(v[j].z, v[j].w)));
    }
    __shared__ float redm[8], reds[8];
    #pragma unroll
    for (int o = 16; o; o >>= 1) m = fmaxf(m, __shfl_xor_sync(0xffffffffu, m, o));
    if ((tid & 31) == 0) redm[tid >> 5] = m;
    __syncthreads();
    float bm = redm[0];
    #pragma unroll
    for (int i = 1; i < 8; i++) bm = fmaxf(bm, redm[i]);

    const float SC = 0.03125f;  // 1/sqrt(1024)
    float s = 0.f;
    #pragma unroll
    for (int j = 0; j < 8; j++) {
        v[j].x = __expf((v[j].x - bm) * SC);
        v[j].y = __expf((v[j].y - bm) * SC);
        v[j].z = __expf((v[j].z - bm) * SC);
        v[j].w = exp_fma((v[j].w - bm) * SC);
        s += (v[j].x + v[j].y) + (v[j].z + v[j].w);
    }
    #pragma unroll
    for (int o = 16; o; o >>= 1) s += __shfl_xor_sync(0xffffffffu, s, o);
    if ((tid & 31) == 0) reds[tid >> 5] = s;
    __syncthreads();
    float tot = 0.f;
    #pragma unroll
    for (int i = 0; i < 8; i++) tot += reds[i];
    const float r = 1.f / tot;

    #pragma unroll
    for (int j = 0; j < 8; j++) {
        v[j].x = f2tf32(v[j].x * r); v[j].y = f2tf32(v[j].y * r);
        v[j].z = f2tf32(v[j].z * r); v[j].w = f2tf32(v[j].w * r);
        p[tid + j * 256] = v[j];
    }
}

// ---------------------------------------------------------------------------
// Host
// ---------------------------------------------------------------------------
typedef CUresult (*PFN_tmapenc)(CUtensorMap*, CUtensorMapDataType, cuuint32_t, void*,
                                const cuuint64_t*, const cuuint64_t*, const cuuint32_t*,
                                const cuuint32_t*, CUtensorMapInterleave, CUtensorMapSwizzle,
                                CUtensorMapL2promotion, CUtensorMapFloatOOBfill);

static void build_map_f32(PFN_tmapenc enc, CUtensorMap* m, float* p,
                          uint64_t rows, uint64_t cols)
{
    cuuint64_t dims[3] = {cols, rows, 1};
    cuuint64_t strides[2] = {cols * 4, rows * cols * 4};
    cuuint32_t box[3] = {16, 256, 1};   // 16 f32 = 64 B rows (SW64)
    cuuint32_t es[3] = {1, 1, 1};
    if (enc)
        enc(m, CU_TENSOR_MAP_DATA_TYPE_FLOAT32, 3, p, dims, strides, box, es,
            CU_TENSOR_MAP_INTERLEAVE_NONE, CU_TENSOR_MAP_SWIZZLE_64B,
            CU_TENSOR_MAP_L2_PROMOTION_L2_128B, CU_TENSOR_MAP_FLOAT_OOB_FILL_NONE);
}
static void build_map_bf16_sw128(PFN_tmapenc enc, CUtensorMap* m, __nv_bfloat16* p,
                                 uint64_t rows, uint64_t cols2)
{
    cuuint64_t dims[3] = {cols2, rows, 1};
    cuuint64_t strides[2] = {cols2 * 2, rows * cols2 * 2};
    cuuint32_t box[3] = {64, 256, 1};   // 64 bf16 = 128 B rows (SW128)
    cuuint32_t es[3] = {1, 1, 1};
    if (enc)
        enc(m, CU_TENSOR_MAP_DATA_TYPE_BFLOAT16, 3, p, dims, strides, box, es,
            CU_TENSOR_MAP_INTERLEAVE_NONE, CU_TENSOR_MAP_SWIZZLE_128B,
            CU_TENSOR_MAP_L2_PROMOTION_L2_128B, CU_TENSOR_MAP_FLOAT_OOB_FILL_NONE);
}

extern "C" void kernel_launch(void* const* d_in, const int* in_sizes, int n_in,
                              void* d_out, int out_size)
{
    const float* x = nullptr;
    const float* w[3] = {nullptr, nullptr, nullptr};
    int wi = 0;
    for (int i = 0; i < n_in; i++) {
        if (in_sizes[i] == SEQ * DIM && x == nullptr) x = (const float*)d_in[i];
        else if (wi < 3) w[wi++] = (const float*)d_in[i];
    }
    float* out = (float*)d_out;

    float *xh, *xl, *wqth, *wqtl, *wkth, *wktl, *wvt;
    float *qh, *ql, *kh, *kl, *vt, *s;
    __nv_bfloat16 *qb, *kb;
    cudaGetSymbolAddress((void**)&xh, g_xh);     cudaGetSymbolAddress((void**)&xl, g_xl);
    cudaGetSymbolAddress((void**)&wqth, g_wqth); cudaGetSymbolAddress((void**)&wqtl, g_wqtl);
    cudaGetSymbolAddress((void**)&wkth, g_wkth); cudaGetSymbolAddress((void**)&wktl, g_wktl);
    cudaGetSymbolAddress((void**)&wvt, g_wvt);
    cudaGetSymbolAddress((void**)&qh, g_qh);     cudaGetSymbolAddress((void**)&ql, g_ql);
    cudaGetSymbolAddress((void**)&qb, g_qb);
    cudaGetSymbolAddress((void**)&kh, g_kh);     cudaGetSymbolAddress((void**)&kl, g_kl);
    cudaGetSymbolAddress((void**)&kb, g_kb);
    cudaGetSymbolAddress((void**)&vt, g_vt);     cudaGetSymbolAddress((void**)&s, g_s);

    void* pfn = nullptr;
    cudaDriverEntryPointQueryResult qr;
    cudaGetDriverEntryPoint("cuTensorMapEncodeTiled", &pfn, cudaEnableDefault, &qr);
    PFN_tmapenc enc = (PFN_tmapenc)pfn;

    CUtensorMap m_xh, m_xl, m_wqth, m_wqtl, m_wkth, m_wktl, m_wvt;
    CUtensorMap m_qb, m_kb, m_vt, m_s;
    build_map_f32(enc, &m_xh, xh, SEQ, DIM);     build_map_f32(enc, &m_xl, xl, SEQ, DIM);
    build_map_f32(enc, &m_wqth, wqth, DIM, DIM); build_map_f32(enc, &m_wqtl, wqtl, DIM, DIM);
    build_map_f32(enc, &m_wkth, wkth, DIM, DIM); build_map_f32(enc, &m_wktl, wktl, DIM, DIM);
    build_map_f32(enc, &m_wvt, wvt, DIM, DIM);
    build_map_bf16_sw128(enc, &m_qb, qb, SEQ, 2 * DIM);
    build_map_bf16_sw128(enc, &m_kb, kb, SEQ, 2 * DIM);
    build_map_f32(enc, &m_vt, vt, DIM, SEQ);
    build_map_f32(enc, &m_s, s, SEQ, SEQ);

    // smem: NMMA3 tc = 3x64KB = 196,608 (+1KB); NMMA2 tc = 3x64KB too;
    // NMMA1 tc = 3x32KB. Fallback needs up to 147,456 — covered.
    const int smemBig = 3 * 4 * 16384 + 1024;   // 197,632
    const int smem1   = 3 * 2 * 16384 + 1024;   //  99,328
    cudaFuncSetAttribute(tc_gemm<3, 4>, cudaFuncAttributeMaxDynamicSharedMemorySize, smemBig);
    cudaFuncSetAttribute(tc_gemm<2, 0>, cudaFuncAttributeMaxDynamicSharedMemorySize, smemBig);
    cudaFuncSetAttribute(tc_gemm<1, 1>, cudaFuncAttributeMaxDynamicSharedMemorySize, smem1);
    cudaFuncSetAttribute(tc_gemm<1, 0>, cudaFuncAttributeMaxDynamicSharedMemorySize, smem1);

    // --- pre-pass (unchanged) ---
    split_kernel<true><<<512, 256>>>(x, xh, xl, SEQ * DIM / 4);
    dim3 tb(32, 8), tg(DIM / 32, DIM / 32);
    transpose_split_kernel<true><<<tg, tb>>>(w[0], wqth, wqtl, DIM, DIM);
    transpose_split_kernel<true><<<tg, tb>>>(w[1], wkth, wktl, DIM, DIM);
    transpose_split_kernel<false><<<tg, tb>>>(w[2], wvt, nullptr, DIM, DIM);

    // --- Q, K projections (tf32 3-term; EPI=4: bf16-interleaved-only output) ---
    dim3 gproj(DIM / BN, SEQ / BM);   // (4, 32)
    tc_gemm<3, 4><<<gproj, 256, smemBig>>>(m_xh, m_xl, m_wqth, m_wqtl,
                                           xh, xl, wqth, wqtl, qh, ql, qb, DIM, DIM);
    tc_gemm<3, 4><<<gproj, 256, smemBig>>>(m_xh, m_xl, m_wkth, m_wktl,
                                           xh, xl, wkth, wktl, kh, kl, kb, DIM, DIM);

    // --- V^T = Wv^T @ X^T (tf32 1x, tf32-rounded out): C[DIM, SEQ] ---
    dim3 gvt(SEQ / BN, DIM / BM);     // (32, 4)
    tc_gemm<1, 1><<<gvt, 256, smem1>>>(m_wvt, m_wvt, m_xh, m_xh,
                                       wvt, wvt, xh, xh, vt, nullptr, nullptr, SEQ, DIM);

    // --- S = Q @ K^T (bf16 3-term, BK=32/SW128 — overhead re-amortized) ---
    dim3 gscore(SEQ / BN, SEQ / BM);  // (32, 32)
    tc_gemm<2, 0><<<gscore, 256, smemBig>>>(m_qb, m_qb, m_kb, m_kb,
                                            qh, ql, kh, kl, s, nullptr, nullptr, SEQ, DIM);

    softmax_rows_kernel<<<SEQ, 256>>>(s);

    // --- out = P @ (V^T)^T (tf32 1x): C[SEQ, DIM] ---
    dim3 gpv(DIM / BN, SEQ / BM);     // (4, 32)
    tc_gemm<1, 0><<<gpv, 256, smem1>>>(m_s, m_s, m_vt, m_vt,
                                       s, s, vt, vt, out, nullptr, nullptr, DIM, SEQ);
}

// round 16
// speedup vs baseline: 1.7434x; 1.3210x over previous
#include <cuda_runtime.h>
#include <cuda.h>
#include <cuda_bf16.h>
#include <cuda_fp16.h>
#include <cstdint>

#define SEQ 8192
#define DIM 1024

// tcgen05 is only legal when compiling the arch-specific (sm_103a) device pass.
#if (defined(__CUDA_ARCH_FEAT_SM103_ALL) || (defined(__CUDA_ARCH_SPECIFIC__) && (__CUDA_ARCH_SPECIFIC__ == 1030)))
#define TC_PATH 1
#else
#define TC_PATH 0
#endif

// ---- device scratch (no allocations allowed) ----
__device__ float g_xh[SEQ * DIM], g_xl[SEQ * DIM];          // x hi/lo fp32 (k-major)
__device__ float g_wqth[DIM * DIM], g_wqtl[DIM * DIM];      // Wq^T hi/lo
__device__ float g_wkth[DIM * DIM], g_wktl[DIM * DIM];      // Wk^T hi/lo
__device__ float g_wvt[DIM * DIM];                          // Wv^T (tf32)
__device__ float g_qh[SEQ * DIM], g_ql[SEQ * DIM];          // Q hi/lo fp32 (fallback only)
__device__ __nv_bfloat16 g_qb[SEQ * 2 * DIM];               // Q bf16 interleaved [hi16|lo16]
__device__ float g_kh[SEQ * DIM], g_kl[SEQ * DIM];          // K hi/lo fp32 (fallback only)
__device__ __nv_bfloat16 g_kb[SEQ * 2 * DIM];               // K bf16 interleaved
__device__ float g_vt[(size_t)DIM * SEQ];                   // V^T fp32 (fallback only)
__device__ __half g_vth[(size_t)DIM * SEQ];                 // V^T fp16 [DIM, SEQ]
__device__ float g_s[(size_t)SEQ * SEQ];                    // raw scores (fp32)
__device__ __half g_sp[(size_t)SEQ * SEQ];                  // softmax weights (fp16)

// ---------------------------------------------------------------------------
// Common helpers
// ---------------------------------------------------------------------------
__device__ __forceinline__ float f2tf32(float f) {
    uint32_t r;
    asm("cvt.rna.tf32.f32 %0, %1;" : "=r"(r) : "f"(f));
    return __uint_as_float(r);
}
__device__ __forceinline__ uint32_t smem_u32(const void* p) {
    uint32_t a;
    asm("{ .reg .u64 t; cvta.to.shared.u64 t, %1; cvt.u32.u64 %0, t; }" : "=r"(a) : "l"(p));
    return a;
}
__device__ __forceinline__ void cp_async16(float* smem_dst, const float* gmem_src) {
    uint32_t s = (uint32_t)__cvta_generic_to_shared(smem_dst);
    asm volatile("cp.async.cg.shared.global [%0], [%1], 16;\n" :: "r"(s), "l"(gmem_src));
}
__device__ __forceinline__ void cp_commit() { asm volatile("cp.async.commit_group;\n"); }
template <int N>
__device__ __forceinline__ void cp_wait() { asm volatile("cp.async.wait_group %0;\n" :: "n"(N)); }

__device__ __forceinline__ void mma_sync_tf32(float* d, const uint32_t* a, const uint32_t* b) {
    asm volatile(
        "mma.sync.aligned.m16n8k8.row.col.f32.tf32.tf32.f32 "
        "{%0,%1,%2,%3}, {%4,%5,%6,%7}, {%8,%9}, {%0,%1,%2,%3};\n"
        : "+f"(d[0]), "+f"(d[1]), "+f"(d[2]), "+f"(d[3])
        : "r"(a[0]), "r"(a[1]), "r"(a[2]), "r"(a[3]), "r"(b[0]), "r"(b[1]));
}

// ---------------------------------------------------------------------------
// mbarrier / TMA helpers
// ---------------------------------------------------------------------------
__device__ __forceinline__ void mbar_init(uint32_t a, uint32_t cnt) {
    asm volatile("mbarrier.init.shared.b64 [%0], %1;" :: "r"(a), "r"(cnt) : "memory");
}
__device__ __forceinline__ void mbar_expect(uint32_t a, uint32_t bytes) {
    asm volatile("mbarrier.arrive.expect_tx.shared.b64 _, [%0], %1;" :: "r"(a), "r"(bytes) : "memory");
}
__device__ __forceinline__ void mbar_wait(uint32_t a, uint32_t parity) {
    asm volatile(
        "{\n\t"
        ".reg .pred P1;\n\t"
        "LAB_WAIT%=:\n\t"
        "mbarrier.try_wait.parity.acquire.cta.shared::cta.b64 P1, [%0], %1, 0x989680;\n\t"
        "@P1 bra LAB_DONE%=;\n\t"
        "bra LAB_WAIT%=;\n\t"
        "LAB_DONE%=:\n\t"
        "}"
        :: "r"(a), "r"(parity) : "memory");
}
__device__ __forceinline__ void tma3d(uint32_t dst, const CUtensorMap* m, int x, int y, uint32_t mbar) {
    asm volatile(
        "cp.async.bulk.tensor.3d.shared::cta.global.tile.mbarrier::complete_tx::bytes "
        "[%0], [%1, {%2, %3, %4}], [%5];"
        :: "r"(dst), "l"(m), "r"(x), "r"(y), "r"(0), "r"(mbar) : "memory");
}
#if TC_PATH
__device__ __forceinline__ void tc_alloc(uint32_t smem_result, uint32_t ncols) {
    asm volatile("tcgen05.alloc.cta_group::1.sync.aligned.shared::cta.b32 [%0], %1;"
                 :: "r"(smem_result), "r"(ncols) : "memory");
}
__device__ __forceinline__ void tc_dealloc(uint32_t tmem, uint32_t ncols) {
    asm volatile("tcgen05.dealloc.cta_group::1.sync.aligned.b32 %0, %1;" :: "r"(tmem), "r"(ncols));
}
__device__ __forceinline__ void tc_commit(uint32_t mbar) {
    asm volatile("tcgen05.commit.cta_group::1.mbarrier::arrive::one.shared::cluster.b64 [%0];"
                 :: "r"(mbar) : "memory");
}
__device__ __forceinline__ void tc_fence_after() {
    asm volatile("tcgen05.fence::after_thread_sync;" ::: "memory");
}
__device__ __forceinline__ void tc_wait_ld() {
    asm volatile("tcgen05.wait::ld.sync.aligned;" ::: "memory");
}
__device__ __forceinline__ void tc_ld_x32(uint32_t* r, uint32_t tmem) {
    asm volatile(
        "tcgen05.ld.sync.aligned.32x32b.x32.b32 "
        "{%0, %1, %2, %3, %4, %5, %6, %7, %8, %9, %10, %11, %12, %13, %14, %15, "
        " %16, %17, %18, %19, %20, %21, %22, %23, %24, %25, %26, %27, %28, %29, %30, %31}, [%32];"
        : "=r"(r[0]), "=r"(r[1]), "=r"(r[2]), "=r"(r[3]), "=r"(r[4]), "=r"(r[5]), "=r"(r[6]), "=r"(r[7]),
          "=r"(r[8]), "=r"(r[9]), "=r"(r[10]), "=r"(r[11]), "=r"(r[12]), "=r"(r[13]), "=r"(r[14]), "=r"(r[15]),
          "=r"(r[16]), "=r"(r[17]), "=r"(r[18]), "=r"(r[19]), "=r"(r[20]), "=r"(r[21]), "=r"(r[22]), "=r"(r[23]),
          "=r"(r[24]), "=r"(r[25]), "=r"(r[26]), "=r"(r[27]), "=r"(r[28]), "=r"(r[29]), "=r"(r[30]), "=r"(r[31])
        : "r"(tmem));
}
__device__ __forceinline__ void mma_ss_tf32(uint32_t d, uint64_t a, uint64_t b, uint32_t idesc, uint32_t en) {
    asm volatile(
        "{\n\t"
        ".reg .pred p;\n\t"
        "setp.ne.u32 p, %4, 0;\n\t"
        "tcgen05.mma.cta_group::1.kind::tf32 [%0], %1, %2, %3, {%5, %5, %5, %5}, p;\n\t"
        "}"
        :: "r"(d), "l"(a), "l"(b), "r"(idesc), "r"(en), "r"(0u) : "memory");
}
__device__ __forceinline__ void mma_ss_f16(uint32_t d, uint64_t a, uint64_t b, uint32_t idesc, uint32_t en) {
    asm volatile(
        "{\n\t"
        ".reg .pred p;\n\t"
        "setp.ne.u32 p, %4, 0;\n\t"
        "tcgen05.mma.cta_group::1.kind::f16 [%0], %1, %2, %3, {%5, %5, %5, %5}, p;\n\t"
        "}"
        :: "r"(d), "l"(a), "l"(b), "r"(idesc), "r"(en), "r"(0u) : "memory");
}
#endif

// SW64 smem descriptor (64B rows): layout=SW64(4), version=1, SBO=32, LBO=1
static constexpr uint64_t DESC_BASE_SW64 =
    (4ull << 61) | (1ull << 46) | (32ull << 32) | (1ull << 16);
__device__ __forceinline__ uint64_t make_desc64(uint32_t addr) {
    return DESC_BASE_SW64 | ((uint64_t)(addr >> 4) & 0x3FFF);
}
// SW128 smem descriptor (128B rows): layout=SW128(2), version=1, SBO=64, LBO=1
static constexpr uint64_t DESC_BASE_SW128 =
    (2ull << 61) | (1ull << 46) | (64ull << 32) | (1ull << 16);
__device__ __forceinline__ uint64_t make_desc128(uint32_t addr) {
    return DESC_BASE_SW128 | ((uint64_t)(addr >> 4) & 0x3FFF);
}

// ---------------------------------------------------------------------------
// Unified GEMM: C[M, Ntot] = A[M, K] * B[Ntot, K]^T.
// NMMA==1: tf32 1x, BK=16, SW64 fp32 tiles.
// NMMA==3: tf32 3-term hi/lo, BK=16, SW64 fp32 hi+lo tiles.
// NMMA==2: bf16 3-term, BK=32, SW128 bf16 interleaved [hi16|lo16] tiles.
// NMMA==4: fp16 1x, BK=64, SW128 plain fp16 tiles (fp16 mantissa == tf32
//          precision at HALF the bytes — PV traffic halved, R15).
// CTA tile 256x256 (two M=128 halves -> TMEM 512 cols), 3-stage TMA pipeline
// with deferred done-waits (R12), 256 threads, no clusters.
// EPI: 0=raw fp32, 1=tf32-rounded fp32, 2=fp32 hi/lo split,
//      4=bf16 interleaved only (Cb), 5=plain fp16 (Cb).
// ---------------------------------------------------------------------------
constexpr int BM = 256, BN = 256;
constexpr int MH = 128;
constexpr uint32_t IDESC_TF32 =
    (1u << 4) | (2u << 7) | (2u << 10) | ((BN / 8) << 17) | ((MH / 16) << 24);
constexpr uint32_t IDESC_BF16 =
    (1u << 4) | (1u << 7) | (1u << 10) | ((BN / 8) << 17) | ((MH / 16) << 24);
constexpr uint32_t IDESC_FP16 =
    (1u << 4) | (0u << 7) | (0u << 10) | ((BN / 8) << 17) | ((MH / 16) << 24);

template <int NMMA, int EPI>
__global__ __launch_bounds__(256, 1)
void tc_gemm(const __grid_constant__ CUtensorMap tmA0,
             const __grid_constant__ CUtensorMap tmA1,
             const __grid_constant__ CUtensorMap tmB0,
             const __grid_constant__ CUtensorMap tmB1,
             const float* __restrict__ Ah, const float* __restrict__ Al,
             const float* __restrict__ Bh, const float* __restrict__ Bl,
             float* __restrict__ C0, float* __restrict__ C1,
             void* __restrict__ Cb,
             int Ntot, int Ktot)
{
    extern __shared__ __align__(16) float smem[];
    const int tid = threadIdx.x;
    const int bn = blockIdx.x * BN;
    const int bm = blockIdx.y * BM;

#if TC_PATH
    // ======================= tcgen05 + TMA path =======================
    constexpr int BK = (NMMA == 4) ? 64 : (NMMA == 2) ? 32 : 16;    // logical K/chunk
    constexpr int T_BYTES = (NMMA == 1 || NMMA == 3) ? 16384 : 32768;
    constexpr int STAGE = (NMMA == 3) ? 4 * 16384 : 2 * T_BYTES;
    constexpr int NS = 3;
    constexpr uint32_t AH1 = (T_BYTES == 32768) ? 1024 : 512;       // A M-half-1 (16B units)
    const int NT = Ktot / BK;

    __shared__ __align__(8) uint64_t mbar_store[2 * NS];
    __shared__ uint32_t tmem_ptr;

    const int wid = tid >> 5;
    const int lid = tid & 31;
    const uint32_t sbase = (smem_u32(smem) + 1023) & ~1023u;
    uint32_t mb_full[NS], mb_done[NS];
    #pragma unroll
    for (int s = 0; s < NS; s++) {
        mb_full[s] = smem_u32(&mbar_store[s]);
        mb_done[s] = smem_u32(&mbar_store[NS + s]);
    }

    if (wid == 0) tc_alloc(smem_u32(&tmem_ptr), 512);
    if (tid == 0) {
        #pragma unroll
        for (int s = 0; s < NS; s++) { mbar_init(mb_full[s], 1); mbar_init(mb_done[s], 1); }
    }
    __syncthreads();
    const uint32_t tmem = tmem_ptr;      // D0 = cols 0-255, D1 = cols 256-511

    if (tid == 0) {
        uint32_t pf[NS] = {};
        const uint32_t boff = (NMMA == 3) ? 2 * 16384 : T_BYTES;

        auto issue = [&](int it, int s) {
            const uint32_t st = sbase + (uint32_t)s * STAGE;
            const int k0 = it * BK;
            mbar_expect(mb_full[s], (uint32_t)STAGE);
            if (NMMA == 2) {
                tma3d(st,        &tmA0, 2 * k0, bm, mb_full[s]);    // bf16 ileaved: x=2k
                tma3d(st + boff, &tmB0, 2 * k0, bn, mb_full[s]);
            } else if (NMMA == 4) {
                tma3d(st,        &tmA0, k0, bm, mb_full[s]);        // fp16 plain: x=k
                tma3d(st + boff, &tmB0, k0, bn, mb_full[s]);
            } else {
                tma3d(st, &tmA0, k0, bm, mb_full[s]);
                if (NMMA == 3) tma3d(st + 16384, &tmA1, k0, bm, mb_full[s]);
                tma3d(st + boff, &tmB0, k0, bn, mb_full[s]);
                if (NMMA == 3) tma3d(st + boff + 16384, &tmB1, k0, bn, mb_full[s]);
            }
        };

        #pragma unroll
        for (int s = 0; s < NS; s++)
            if (s < NT) issue(s, s);

        for (int it = 0; it < NT; it++) {
            const int s = it % NS;
            mbar_wait(mb_full[s], pf[s]); pf[s] ^= 1;

            const uint32_t st = sbase + (uint32_t)s * STAGE;

            if (NMMA == 2) {
                // SW128 bf16 ileaved: two 16-K groups {hi,lo} at units {0,2,4,6}
                const uint64_t da = make_desc128(st);
                const uint64_t db = make_desc128(st + boff);
                #pragma unroll
                for (int ks = 0; ks < 2; ks++) {
                    const uint64_t o = 4 * ks;
                    const uint32_t en0 = (it > 0 || ks > 0) ? 1u : 0u;
                    #pragma unroll
                    for (int h = 0; h < 2; h++) {
                        const uint32_t d = tmem + h * 256;
                        const uint64_t ha = h * (uint64_t)AH1;
                        mma_ss_f16(d, da + ha + o,     db + o,     IDESC_BF16, en0);
                        mma_ss_f16(d, da + ha + o,     db + o + 2, IDESC_BF16, 1u);
                        mma_ss_f16(d, da + ha + o + 2, db + o,     IDESC_BF16, 1u);
                    }
                }
            } else if (NMMA == 4) {
                // SW128 fp16 plain: four 16-K groups at units {0,2,4,6}
                const uint64_t da = make_desc128(st);
                const uint64_t db = make_desc128(st + boff);
                #pragma unroll
                for (int g = 0; g < 4; g++) {
                    const uint64_t o = 2 * g;
                    const uint32_t en0 = (it > 0 || g > 0) ? 1u : 0u;
                    #pragma unroll
                    for (int h = 0; h < 2; h++) {
                        mma_ss_f16(tmem + h * 256, da + h * (uint64_t)AH1 + o, db + o,
                                   IDESC_FP16, en0);
                    }
                }
            } else {
                const uint64_t da0 = make_desc64(st);
                const uint64_t db0 = make_desc64(st + boff);
                const uint64_t da1 = make_desc64(st + 16384);
                const uint64_t db1 = make_desc64(st + boff + 16384);
                #pragma unroll
                for (int ks = 0; ks < 2; ks++) {            // two K=8 steps
                    const uint64_t o = 2 * ks;
                    const uint32_t en0 = (it > 0 || ks > 0) ? 1u : 0u;
                    #pragma unroll
                    for (int h = 0; h < 2; h++) {
                        const uint32_t d = tmem + h * 256;
                        const uint64_t ha = h * (uint64_t)AH1;
                        if (NMMA == 3) {
                            mma_ss_tf32(d, da0 + ha + o, db1 + o, IDESC_TF32, en0);
                            mma_ss_tf32(d, da1 + ha + o, db0 + o, IDESC_TF32, 1u);
                            mma_ss_tf32(d, da0 + ha + o, db0 + o, IDESC_TF32, 1u);
                        } else {
                            mma_ss_tf32(d, da0 + ha + o, db0 + o, IDESC_TF32, en0);
                        }
                    }
                }
            }
            tc_commit(mb_done[s]);

            // Deferred refill (R12): current chunk's MMAs are already queued,
            // keeping the tensor pipe busy while we wait on the PREVIOUS chunk.
            const int prev = it - 1;
            if (prev >= 0 && prev + NS < NT) {
                const int sp = prev % NS;
                mbar_wait(mb_done[sp], (uint32_t)((prev / NS) & 1));
                issue(prev + NS, sp);
            }
        }
        mbar_wait(mb_done[(NT - 1) % NS], (uint32_t)(((NT - 1) / NS) & 1));
    }
    __syncthreads();
    tc_fence_after();

    // epilogue: warps 0-3; each D half is 128 rows x 256 cols fp32
    if (wid < 4) {
        #pragma unroll
        for (int h = 0; h < 2; h++) {
            const size_t row = (size_t)(bm + h * MH + wid * 32 + lid);
            const uint32_t dbase = tmem + h * 256;
            #pragma unroll
            for (int cb = 0; cb < BN / 32; cb++) {
                uint32_t r[32];
                tc_ld_x32(r, dbase + cb * 32);
                tc_wait_ld();
                if (EPI == 4) {
                    __nv_bfloat16* db = (__nv_bfloat16*)Cb
                        + row * (size_t)(2 * Ntot) + 2 * (size_t)bn + 64 * cb;
                    #pragma unroll
                    for (int i = 0; i < 32; i += 4) {
                        float a = __uint_as_float(r[i]),   b = __uint_as_float(r[i+1]);
                        float c = __uint_as_float(r[i+2]), d = __uint_as_float(r[i+3]);
                        __nv_bfloat162 h01 = __floats2bfloat162_rn(a, b);
                        __nv_bfloat162 h23 = __floats2bfloat162_rn(c, d);
                        float la = a - __bfloat162float(h01.x);
                        float lb = b - __bfloat162float(h01.y);
                        float lc = c - __bfloat162float(h23.x);
                        float ld = d - __bfloat162float(h23.y);
                        int base = 32 * (i >> 4) + (i & 15);
                        *(__nv_bfloat162*)(db + base)      = h01;
                        *(__nv_bfloat162*)(db + base + 2)  = h23;
                        *(__nv_bfloat162*)(db + base + 16) = __floats2bfloat162_rn(la, lb);
                        *(__nv_bfloat162*)(db + base + 18) = __floats2bfloat162_rn(lc, ld);
                    }
                } else if (EPI == 5) {
                    __half* dh = (__half*)Cb + row * (size_t)Ntot + bn + cb * 32;
                    #pragma unroll
                    for (int i = 0; i < 32; i += 4) {
                        float a = __uint_as_float(r[i]),   b = __uint_as_float(r[i+1]);
                        float c = __uint_as_float(r[i+2]), d = __uint_as_float(r[i+3]);
                        *(__half2*)(dh + i)     = __floats2half2_rn(a, b);
                        *(__half2*)(dh + i + 2) = __floats2half2_rn(c, d);
                    }
                } else {
                    float* d0 = C0 + row * (size_t)Ntot + bn + cb * 32;
                    if (EPI == 2) {
                        float* d1 = C1 + row * (size_t)Ntot + bn + cb * 32;
                        #pragma unroll
                        for (int i = 0; i < 32; i += 4) {
                            float a = __uint_as_float(r[i]),   b = __uint_as_float(r[i+1]);
                            float c = __uint_as_float(r[i+2]), d = __uint_as_float(r[i+3]);
                            float ha = f2tf32(a), hb = f2tf32(b), hc = f2tf32(c), hd = f2tf32(d);
                            *(float4*)(d0 + i) = make_float4(ha, hb, hc, hd);
                            *(float4*)(d1 + i) = make_float4(f2tf32(a - ha), f2tf32(b - hb),
                                                             f2tf32(c - hc), f2tf32(d - hd));
                        }
                    } else {
                        #pragma unroll
                        for (int i = 0; i < 32; i += 4) {
                            float a = __uint_as_float(r[i]),   b = __uint_as_float(r[i+1]);
                            float c = __uint_as_float(r[i+2]), d = __uint_as_float(r[i+3]);
                            if (EPI == 1) { a = f2tf32(a); b = f2tf32(b); c = f2tf32(c); d = f2tf32(d); }
                            *(float4*)(d0 + i) = make_float4(a, b, c, d);
                        }
                    }
                }
            }
        }
    }
    __syncthreads();
    if (wid == 0) tc_dealloc(tmem, 512);

#else
    // ============== mma.sync fallback (compile-only; sm_103a cubin runs). ====
    constexpr bool THREE = (NMMA == 2 || NMMA == 3);
    constexpr int BKF = 32;
    constexpr int AST = BKF + 4;
    constexpr int A_ELEMS = 128 * AST;
    constexpr int B_ELEMS = 128 * AST;
    constexpr int STAGE = THREE ? 2 * (A_ELEMS + B_ELEMS) : (A_ELEMS + B_ELEMS);
    const int NTF = Ktot / BKF;

    const int lane = tid & 31;
    const int warp = tid >> 5;
    const int wm = (warp & 1) * 64;
    const int wn = (warp >> 1) * 32;
    const int g  = lane >> 2;
    const int t4 = lane & 3;
    const int ar = tid >> 3;
    const int ac = (tid & 7) * 4;

    for (int mh = 0; mh < 2; mh++) {
        const int bm2 = bm + mh * 128;
        for (int nh = 0; nh < 2; nh++) {
            const int bn2 = bn + nh * 128;

            float acc[4][4][4];
            #pragma unroll
            for (int mt = 0; mt < 4; mt++)
                #pragma unroll
                for (int nt = 0; nt < 4; nt++)
                    #pragma unroll
                    for (int i = 0; i < 4; i++) acc[mt][nt][i] = 0.f;

            auto issue_tile = [&](int it, int buf) {
                const int k0 = it * BKF;
                float* a_h = smem + buf * STAGE;
                float* a_l = a_h + A_ELEMS;
                float* b_h = THREE ? a_l + A_ELEMS : a_h + A_ELEMS;
                float* b_l = b_h + B_ELEMS;
                #pragma unroll
                for (int p = 0; p < 4; p++) {
                    int r = ar + p * 32;
                    size_t off = (size_t)(bm2 + r) * Ktot + k0 + ac;
                    cp_async16(&a_h[r * AST + ac], Ah + off);
                    if (THREE) cp_async16(&a_l[r * AST + ac], Al + off);
                }
                #pragma unroll
                for (int p = 0; p < 4; p++) {
                    int n = ar + p * 32;
                    size_t off = (size_t)(bn2 + n) * Ktot + k0 + ac;
                    cp_async16(&b_h[n * AST + ac], Bh + off);
                    if (THREE) cp_async16(&b_l[n * AST + ac], Bl + off);
                }
                cp_commit();
            };

            issue_tile(0, 0);

            for (int it = 0; it < NTF; it++) {
                const bool has_next = (it + 1 < NTF);
                if (has_next) issue_tile(it + 1, (it + 1) & 1);
                if (has_next) cp_wait<1>(); else cp_wait<0>();
                __syncthreads();

                const float* a_h = smem + (it & 1) * STAGE;
                const float* a_l = a_h + A_ELEMS;
                const float* b_h = THREE ? a_l + A_ELEMS : a_h + A_ELEMS;
                const float* b_l = b_h + B_ELEMS;

                #pragma unroll
                for (int kk = 0; kk < 4; kk++) {
                    const int k = kk * 8;
                    uint32_t bh[4][2], bl[4][2];
                    #pragma unroll
                    for (int nt = 0; nt < 4; nt++) {
                        int c = wn + nt * 8 + g;
                        #pragma unroll
                        for (int j = 0; j < 2; j++) {
                            int idx = c * AST + k + 4 * j + t4;
                            bh[nt][j] = __float_as_uint(b_h[idx]);
                            if (THREE) bl[nt][j] = __float_as_uint(b_l[idx]);
                        }
                    }
                    #pragma unroll
                    for (int mt = 0; mt < 4; mt++) {
                        int r0 = wm + mt * 16 + g;
                        int i0 = r0 * AST + k + t4;
                        int i1 = (r0 + 8) * AST + k + t4;
                        uint32_t ah[4], al[4];
                        ah[0] = __float_as_uint(a_h[i0]);     ah[1] = __float_as_uint(a_h[i1]);
                        ah[2] = __float_as_uint(a_h[i0 + 4]); ah[3] = __float_as_uint(a_h[i1 + 4]);
                        if (THREE) {
                            al[0] = __float_as_uint(a_l[i0]);     al[1] = __float_as_uint(a_l[i1]);
                            al[2] = __float_as_uint(a_l[i0 + 4]); al[3] = __float_as_uint(a_l[i1 + 4]);
                        }
                        #pragma unroll
                        for (int nt = 0; nt < 4; nt++) {
                            if (THREE) {
                                mma_sync_tf32(acc[mt][nt], ah, bl[nt]);
                                mma_sync_tf32(acc[mt][nt], al, bh[nt]);
                            }
                            mma_sync_tf32(acc[mt][nt], ah, bh[nt]);
                        }
                    }
                }
                __syncthreads();
            }

            #pragma unroll
            for (int mt = 0; mt < 4; mt++) {
                #pragma unroll
                for (int nt = 0; nt < 4; nt++) {
                    int m0 = bm2 + wm + mt * 16 + g;
                    int n0 = bn2 + wn + nt * 8 + 2 * t4;
                    size_t o0 = (size_t)m0 * Ntot + n0;
                    size_t o1 = (size_t)(m0 + 8) * Ntot + n0;
                    float v0 = acc[mt][nt][0], v1 = acc[mt][nt][1];
                    float v2 = acc[mt][nt][2], v3 = acc[mt][nt][3];
                    if (EPI >= 2) {
                        float h0 = f2tf32(v0), h1 = f2tf32(v1), h2 = f2tf32(v2), h3 = f2tf32(v3);
                        *(float2*)&C0[o0] = make_float2(h0, h1);
                        *(float2*)&C0[o1] = make_float2(h2, h3);
                        *(float2*)&C1[o0] = make_float2(f2tf32(v0 - h0), f2tf32(v1 - h1));
                        *(float2*)&C1[o1] = make_float2(f2tf32(v2 - h2), f2tf32(v3 - h3));
                    } else {
                        if (EPI == 1) { v0 = f2tf32(v0); v1 = f2tf32(v1); v2 = f2tf32(v2); v3 = f2tf32(v3); }
                        *(float2*)&C0[o0] = make_float2(v0, v1);
                        *(float2*)&C0[o1] = make_float2(v2, v3);
                    }
                }
            }
            __syncthreads();
        }
    }
#endif
}

// ---------------------------------------------------------------------------
// Pre-pass kernels (unchanged)
// ---------------------------------------------------------------------------
template <bool LO>
__global__ void split_kernel(const float* __restrict__ src, float* __restrict__ hi,
                             float* __restrict__ lo, int n4)
{
    int i = blockIdx.x * blockDim.x + threadIdx.x;
    int stride = gridDim.x * blockDim.x;
    for (; i < n4; i += stride) {
        float4 v = ((const float4*)src)[i];
        float4 h = make_float4(f2tf32(v.x), f2tf32(v.y), f2tf32(v.z), f2tf32(v.w));
        ((float4*)hi)[i] = h;
        if (LO) {
            ((float4*)lo)[i] = make_float4(f2tf32(v.x - h.x), f2tf32(v.y - h.y),
                                           f2tf32(v.z - h.z), f2tf32(v.w - h.w));
        }
    }
}

template <bool LO>
__global__ void transpose_split_kernel(const float* __restrict__ src,
                                       float* __restrict__ dh, float* __restrict__ dl,
                                       int R, int C)
{
    __shared__ float t[32][33];
    const int bx = blockIdx.x * 32, by = blockIdx.y * 32;
    const int tx = threadIdx.x, ty = threadIdx.y;    // block (32, 8)
    #pragma unroll
    for (int j = 0; j < 32; j += 8)
        t[ty + j][tx] = src[(size_t)(by + ty + j) * C + bx + tx];
    __syncthreads();
    #pragma unroll
    for (int j = 0; j < 32; j += 8) {
        float v = t[tx][ty + j];
        float h = f2tf32(v);
        size_t o = (size_t)(bx + ty + j) * R + by + tx;
        dh[o] = h;
        if (LO) dl[o] = f2tf32(v - h);
    }
}

// Fast exp for t <= 0 on the FMA/ALU pipes. Rel err ~1e-7.
__device__ __forceinline__ float exp_fma(float t) {
    float r = t * 1.4426950408889634f;
    r = fmaxf(r, -125.0f);
    float rr = r + 12582912.0f;
    float ri = rr - 12582912.0f;
    float f = r - ri;
    int   i = (int)ri;
    float p = 1.54035304e-4f;
    p = fmaf(p, f, 1.33335581e-3f);
    p = fmaf(p, f, 9.61812911e-3f);
    p = fmaf(p, f, 5.55041087e-2f);
    p = fmaf(p, f, 2.40226507e-1f);
    p = fmaf(p, f, 6.93147181e-1f);
    p = fmaf(p, f, 1.0f);
    return __int_as_float(__float_as_int(p) + (i << 23));
}

// Row softmax: reads raw fp32 S, writes NORMALIZED fp16 P (half the write
// traffic; fp16 mantissa == tf32 precision for values in [0,1]).
__global__ __launch_bounds__(256)
void softmax_rows_kernel(const float* __restrict__ S, __half* __restrict__ P)
{
    const int row = blockIdx.x;
    const float4* p = (const float4*)(S + (size_t)row * SEQ);
    __half* q = P + (size_t)row * SEQ;
    const int tid = threadIdx.x;

    float4 v[8];
    float m = -1e30f;
    #pragma unroll
    for (int j = 0; j < 8; j++) {
        v[j] = p[tid + j * 256];
        m = fmaxf(m, fmaxf(fmaxf(v[j].x, v[j].y), fmaxf(v[j].z, v[j].w)));
    }
    __shared__ float redm[8], reds[8];
    #pragma unroll
    for (int o = 16; o; o >>= 1) m = fmaxf(m, __shfl_xor_sync(0xffffffffu, m, o));
    if ((tid & 31) == 0) redm[tid >> 5] = m;
    __syncthreads();
    float bm = redm[0];
    #pragma unroll
    for (int i = 1; i < 8; i++) bm = fmaxf(bm, redm[i]);

    const float SC = 0.03125f;  // 1/sqrt(1024)
    float s = 0.f;
    #pragma unroll
    for (int j = 0; j < 8; j++) {
        v[j].x = __expf((v[j].x - bm) * SC);
        v[j].y = __expf((v[j].y - bm) * SC);
        v[j].z = __expf((v[j].z - bm) * SC);
        v[j].w = exp_fma((v[j].w - bm) * SC);
        s += (v[j].x + v[j].y) + (v[j].z + v[j].w);
    }
    #pragma unroll
    for (int o = 16; o; o >>= 1) s += __shfl_xor_sync(0xffffffffu, s, o);
    if ((tid & 31) == 0) reds[tid >> 5] = s;
    __syncthreads();
    float tot = 0.f;
    #pragma unroll
    for (int i = 0; i < 8; i++) tot += reds[i];
    const float r = 1.f / tot;

    #pragma unroll
    for (int j = 0; j < 8; j++) {
        int idx = 4 * (tid + j * 256);
        *(__half2*)(q + idx)     = __floats2half2_rn(v[j].x * r, v[j].y * r);
        *(__half2*)(q + idx + 2) = __floats2half2_rn(v[j].z * r, v[j].w * r);
    }
}

// ---------------------------------------------------------------------------
// Host
// ---------------------------------------------------------------------------
typedef CUresult (*PFN_tmapenc)(CUtensorMap*, CUtensorMapDataType, cuuint32_t, void*,
                                const cuuint64_t*, const cuuint64_t*, const cuuint32_t*,
                                const cuuint32_t*, CUtensorMapInterleave, CUtensorMapSwizzle,
                                CUtensorMapL2promotion, CUtensorMapFloatOOBfill);

static void build_map_f32(PFN_tmapenc enc, CUtensorMap* m, float* p,
                          uint64_t rows, uint64_t cols)
{
    cuuint64_t dims[3] = {cols, rows, 1};
    cuuint64_t strides[2] = {cols * 4, rows * cols * 4};
    cuuint32_t box[3] = {16, 256, 1};   // 16 f32 = 64 B rows (SW64)
    cuuint32_t es[3] = {1, 1, 1};
    if (enc)
        enc(m, CU_TENSOR_MAP_DATA_TYPE_FLOAT32, 3, p, dims, strides, box, es,
            CU_TENSOR_MAP_INTERLEAVE_NONE, CU_TENSOR_MAP_SWIZZLE_64B,
            CU_TENSOR_MAP_L2_PROMOTION_L2_128B, CU_TENSOR_MAP_FLOAT_OOB_FILL_NONE);
}
static void build_map_16b(PFN_tmapenc enc, CUtensorMap* m, void* p,
                          uint64_t rows, uint64_t cols2, CUtensorMapDataType dt)
{
    cuuint64_t dims[3] = {cols2, rows, 1};
    cuuint64_t strides[2] = {cols2 * 2, rows * cols2 * 2};
    cuuint32_t box[3] = {64, 256, 1};   // 64 x 2B = 128 B rows (SW128)
    cuuint32_t es[3] = {1, 1, 1};
    if (enc)
        enc(m, dt, 3, p, dims, strides, box, es,
            CU_TENSOR_MAP_INTERLEAVE_NONE, CU_TENSOR_MAP_SWIZZLE_128B,
            CU_TENSOR_MAP_L2_PROMOTION_L2_128B, CU_TENSOR_MAP_FLOAT_OOB_FILL_NONE);
}

extern "C" void kernel_launch(void* const* d_in, const int* in_sizes, int n_in,
                              void* d_out, int out_size)
{
    const float* x = nullptr;
    const float* w[3] = {nullptr, nullptr, nullptr};
    int wi = 0;
    for (int i = 0; i < n_in; i++) {
        if (in_sizes[i] == SEQ * DIM && x == nullptr) x = (const float*)d_in[i];
        else if (wi < 3) w[wi++] = (const float*)d_in[i];
    }
    float* out = (float*)d_out;

    float *xh, *xl, *wqth, *wqtl, *wkth, *wktl, *wvt;
    float *qh, *ql, *kh, *kl, *vt, *s;
    __nv_bfloat16 *qb, *kb;
    __half *vth, *sp;
    cudaGetSymbolAddress((void**)&xh, g_xh);     cudaGetSymbolAddress((void**)&xl, g_xl);
    cudaGetSymbolAddress((void**)&wqth, g_wqth); cudaGetSymbolAddress((void**)&wqtl, g_wqtl);
    cudaGetSymbolAddress((void**)&wkth, g_wkth); cudaGetSymbolAddress((void**)&wktl, g_wktl);
    cudaGetSymbolAddress((void**)&wvt, g_wvt);
    cudaGetSymbolAddress((void**)&qh, g_qh);     cudaGetSymbolAddress((void**)&ql, g_ql);
    cudaGetSymbolAddress((void**)&qb, g_qb);
    cudaGetSymbolAddress((void**)&kh, g_kh);     cudaGetSymbolAddress((void**)&kl, g_kl);
    cudaGetSymbolAddress((void**)&kb, g_kb);
    cudaGetSymbolAddress((void**)&vt, g_vt);     cudaGetSymbolAddress((void**)&vth, g_vth);
    cudaGetSymbolAddress((void**)&s, g_s);       cudaGetSymbolAddress((void**)&sp, g_sp);

    void* pfn = nullptr;
    cudaDriverEntryPointQueryResult qr;
    cudaGetDriverEntryPoint("cuTensorMapEncodeTiled", &pfn, cudaEnableDefault, &qr);
    PFN_tmapenc enc = (PFN_tmapenc)pfn;

    CUtensorMap m_xh, m_xl, m_wqth, m_wqtl, m_wkth, m_wktl, m_wvt;
    CUtensorMap m_qb, m_kb, m_vth, m_sp;
    build_map_f32(enc, &m_xh, xh, SEQ, DIM);     build_map_f32(enc, &m_xl, xl, SEQ, DIM);
    build_map_f32(enc, &m_wqth, wqth, DIM, DIM); build_map_f32(enc, &m_wqtl, wqtl, DIM, DIM);
    build_map_f32(enc, &m_wkth, wkth, DIM, DIM); build_map_f32(enc, &m_wktl, wktl, DIM, DIM);
    build_map_f32(enc, &m_wvt, wvt, DIM, DIM);
    build_map_16b(enc, &m_qb, qb, SEQ, 2 * DIM, CU_TENSOR_MAP_DATA_TYPE_BFLOAT16);
    build_map_16b(enc, &m_kb, kb, SEQ, 2 * DIM, CU_TENSOR_MAP_DATA_TYPE_BFLOAT16);
    build_map_16b(enc, &m_vth, vth, DIM, SEQ, CU_TENSOR_MAP_DATA_TYPE_FLOAT16);
    build_map_16b(enc, &m_sp, sp, SEQ, SEQ, CU_TENSOR_MAP_DATA_TYPE_FLOAT16);

    // smem: NMMA3/2/4 tc = 3 x 64 KB (+1KB); NMMA1 tc = 3 x 32 KB.
    // Fallback needs up to 147,456 — covered by smemBig.
    const int smemBig = 3 * 4 * 16384 + 1024;   // 197,632
    const int smem1   = 3 * 2 * 16384 + 1024;   //  99,328
    cudaFuncSetAttribute(tc_gemm<3, 4>, cudaFuncAttributeMaxDynamicSharedMemorySize, smemBig);
    cudaFuncSetAttribute(tc_gemm<2, 0>, cudaFuncAttributeMaxDynamicSharedMemorySize, smemBig);
    cudaFuncSetAttribute(tc_gemm<1, 5>, cudaFuncAttributeMaxDynamicSharedMemorySize, smem1);
    cudaFuncSetAttribute(tc_gemm<4, 0>, cudaFuncAttributeMaxDynamicSharedMemorySize, smemBig);

    // --- pre-pass (unchanged) ---
    split_kernel<true><<<512, 256>>>(x, xh, xl, SEQ * DIM / 4);
    dim3 tb(32, 8), tg(DIM / 32, DIM / 32);
    transpose_split_kernel<true><<<tg, tb>>>(w[0], wqth, wqtl, DIM, DIM);
    transpose_split_kernel<true><<<tg, tb>>>(w[1], wkth, wktl, DIM, DIM);
    transpose_split_kernel<false><<<tg, tb>>>(w[2], wvt, nullptr, DIM, DIM);

    // --- Q, K projections (tf32 3-term; EPI=4: bf16-interleaved-only out) ---
    dim3 gproj(DIM / BN, SEQ / BM);   // (4, 32)
    tc_gemm<3, 4><<<gproj, 256, smemBig>>>(m_xh, m_xl, m_wqth, m_wqtl,
                                           xh, xl, wqth, wqtl, qh, ql, qb, DIM, DIM);
    tc_gemm<3, 4><<<gproj, 256, smemBig>>>(m_xh, m_xl, m_wkth, m_wktl,
                                           xh, xl, wkth, wktl, kh, kl, kb, DIM, DIM);

    // --- V^T = Wv^T @ X^T (tf32 1x; EPI=5: fp16 out): C[DIM, SEQ] ---
    dim3 gvt(SEQ / BN, DIM / BM);     // (32, 4)
    tc_gemm<1, 5><<<gvt, 256, smem1>>>(m_wvt, m_wvt, m_xh, m_xh,
                                       wvt, wvt, xh, xh, vt, nullptr, vth, SEQ, DIM);

    // --- S = Q @ K^T (bf16 3-term, BK=32/SW128): raw fp32 out ---
    dim3 gscore(SEQ / BN, SEQ / BM);  // (32, 32)
    tc_gemm<2, 0><<<gscore, 256, smemBig>>>(m_qb, m_qb, m_kb, m_kb,
                                            qh, ql, kh, kl, s, nullptr, nullptr, SEQ, DIM);

    softmax_rows_kernel<<<SEQ, 256>>>(s, sp);

    // --- out = P @ (V^T)^T (fp16 1x, BK=64 — PV traffic halved): fp32 out ---
    dim3 gpv(DIM / BN, SEQ / BM);     // (4, 32)
    tc_gemm<4, 0><<<gpv, 256, smemBig>>>(m_sp, m_sp, m_vth, m_vth,
                                         s, s, vt, vt, out, nullptr, nullptr, DIM, SEQ);
}